// round 9
// baseline (speedup 1.0000x reference)
#include <cuda_runtime.h>
#include <cuda_bf16.h>
#include <math.h>
#include <stdint.h>

static constexpr int B_   = 8;
static constexpr int H_   = 128;
static constexpr int W_   = 200;
static constexpr int HW_  = H_ * W_;
static constexpr int C1   = 48;
static constexpr int C2   = 64;
static constexpr int D1_  = C1 * HW_;
static constexpr int BD1_ = B_ * D1_;
static constexpr int BD2_ = B_ * C2 * HW_;
static constexpr int MH   = 5;
static constexpr int MAXIT = 25;
static constexpr float EPS_ = 1e-5f;
static constexpr int D1Q  = D1_ / 4;
static constexpr int BD1Q = BD1_ / 4;
static constexpr int HWQ  = HW_ / 4;
static constexpr int NCHUNK = 100;
static constexpr int PER4   = D1Q / NCHUNK;

__device__ alignas(16) float g_X[(size_t)MH * BD1_];
__device__ alignas(16) float g_F[(size_t)MH * BD1_];
__device__ alignas(16) float g_G[(size_t)MH * BD1_];
__device__ alignas(16) float g_h[BD1_];
__device__ alignas(16) float g_t64[BD2_];
__device__ alignas(16) float g_u48[BD1_];
__device__ alignas(16) float g_w48[BD1_];
__device__ alignas(16) float g_zfin[BD1_];
__device__ float g_n1[B_ * C2 * 2];
__device__ float g_n2[B_ * C1 * 2];
__device__ float g_n3[B_ * C1 * 2];
__device__ float g_bnP[C1 * 2];
__device__ float g_Hm[B_ * MH * MH];
__device__ float g_alpha[B_ * MH];
__device__ float g_Hpart[B_ * NCHUNK * 15];
__device__ float2 g_p1[1024 * 8];
__device__ float2 g_p2b[1024 * 48];
__device__ float2 g_p3[9600];
// B-fragment tables: [tap][ks][oc8][lane] -> uint4(bh0,bh1,bl0,bl1)
__device__ alignas(16) uint4 g_wf1[9 * 3 * 8 * 32];
__device__ alignas(16) uint4 g_wf2[9 * 4 * 6 * 32];

__device__ __forceinline__ uint32_t smem_u32(const void* p) {
    uint32_t a;
    asm("{ .reg .u64 t; cvta.to.shared.u64 t, %1; cvt.u32.u64 %0, t; }" : "=r"(a) : "l"(p));
    return a;
}
__device__ __forceinline__ void ldsm4(uint32_t* r, uint32_t addr) {
    asm volatile("ldmatrix.sync.aligned.m8n8.x4.shared.b16 {%0,%1,%2,%3}, [%4];"
                 : "=r"(r[0]), "=r"(r[1]), "=r"(r[2]), "=r"(r[3]) : "r"(addr));
}
__device__ __forceinline__ void mma16816(float* d, const uint32_t* a, uint32_t b0, uint32_t b1) {
    asm volatile("mma.sync.aligned.m16n8k16.row.col.f32.bf16.bf16.f32 "
                 "{%0,%1,%2,%3}, {%4,%5,%6,%7}, {%8,%9}, {%0,%1,%2,%3};"
                 : "+f"(d[0]), "+f"(d[1]), "+f"(d[2]), "+f"(d[3])
                 : "r"(a[0]), "r"(a[1]), "r"(a[2]), "r"(a[3]), "r"(b0), "r"(b1));
}
__device__ __forceinline__ void bfsplit(float v, uint16_t& h, uint16_t& l) {
    __nv_bfloat16 hb = __float2bfloat16(v);
    __nv_bfloat16 lb = __float2bfloat16(v - __bfloat162float(hb));
    h = __bfloat16_as_ushort(hb); l = __bfloat16_as_ushort(lb);
}
__device__ __forceinline__ uint32_t packh(float a, float b) {
    __nv_bfloat16 ha = __float2bfloat16(a), hb = __float2bfloat16(b);
    return (uint32_t)__bfloat16_as_ushort(ha) | ((uint32_t)__bfloat16_as_ushort(hb) << 16);
}
__device__ __forceinline__ uint32_t packl(float a, float b) {
    __nv_bfloat16 ha = __float2bfloat16(a), hb = __float2bfloat16(b);
    float la = a - __bfloat162float(ha), lb = b - __bfloat162float(hb);
    return (uint32_t)__bfloat16_as_ushort(__float2bfloat16(la))
         | ((uint32_t)__bfloat16_as_ushort(__float2bfloat16(lb)) << 16);
}

__global__ void pack_frag_k(const float* __restrict__ w, uint4* __restrict__ wf,
                            int cin, int noc, int ksteps) {
    int i = blockIdx.x * blockDim.x + threadIdx.x;
    int total = 9 * ksteps * (noc / 8) * 32;
    if (i >= total) return;
    int l = i & 31;
    int rest = i >> 5;
    int j = rest % (noc / 8); rest /= (noc / 8);
    int ks = rest % ksteps;
    int t = rest / ksteps;
    int oc = j * 8 + (l >> 2);
    int cb = ks * 16 + (l & 3) * 2;
    float va = (cb     < cin) ? w[(oc * cin + cb) * 9 + t] : 0.f;
    float vb = (cb + 1 < cin) ? w[(oc * cin + cb + 1) * 9 + t] : 0.f;
    float vc = (cb + 8 < cin) ? w[(oc * cin + cb + 8) * 9 + t] : 0.f;
    float vd = (cb + 9 < cin) ? w[(oc * cin + cb + 9) * 9 + t] : 0.f;
    wf[i] = make_uint4(packh(va, vb), packh(vc, vd), packl(va, vb), packl(vc, vd));
}

// ============ mma.sync 3x3 conv: 2 rows/block, sync-free tap loop ============
// grid (2 xt, 64 y2, 8 b), 256 thr, 8 warps = 4 m-groups x 2 n-groups.
// Product-major mma order: accumulator reuse distance = NT independent mmas.
template <int CIN, int KS, int KPB, int NOC, int NT,
          bool NORMIN, bool RELU, bool ADDRES, bool GN1S, bool GN2S>
__global__ __launch_bounds__(256, 1) void conv_mma_k(
    const float* __restrict__ in, const uint4* __restrict__ wf,
    const float* __restrict__ normP, const float* __restrict__ res,
    float* __restrict__ out) {
    extern __shared__ char smem[];
    constexpr int MT = 4;
    constexpr int NP   = 520;          // 4 slab rows x 130 px
    constexpr int KPW  = KPB / 4;
    constexpr int SLAB = NP * KPB;
    const int tid  = threadIdx.x;
    const int lane = tid & 31;
    const int wrp  = tid >> 5;
    const int xt = blockIdx.x;
    const int y2 = blockIdx.y;
    const int b  = blockIdx.z;
    const int x0 = xt ? (W_ - 128) : 0;
    const int m_base = (wrp >> 1) * (MT * 16);
    const int ng = wrp & 1;

    {
        uint4* z4 = reinterpret_cast<uint4*>(smem);
        for (int i = tid; i < 2 * SLAB / 16; i += 256) z4[i] = make_uint4(0, 0, 0, 0);
    }
    __syncthreads();

    {
        uint32_t* sH = reinterpret_cast<uint32_t*>(smem);
        uint32_t* sL = sH + SLAB / 4;
        const float* inB = in + (size_t)b * CIN * HW_;
        for (int pp = tid; pp < NP; pp += 256) {
            int r = pp / 130, col = pp - r * 130;
            int gy = y2 * 2 - 1 + r, gx = x0 - 1 + col;
            if (gy < 0 || gy >= H_ || gx < 0 || gx >= W_) continue;
            const float* p0 = inB + gy * W_ + gx;
            uint32_t so = pp * KPW;
#pragma unroll 4
            for (int cp = 0; cp < CIN / 2; cp++) {
                float v0 = __ldg(p0 + (size_t)(2 * cp) * HW_);
                float v1 = __ldg(p0 + (size_t)(2 * cp + 1) * HW_);
                if (NORMIN) {
                    const float* np0 = normP + (b * CIN + 2 * cp) * 2;
                    v0 = v0 * np0[0] + np0[1];
                    v1 = v1 * np0[2] + np0[3];
                }
                uint16_t h0, l0, h1, l1;
                bfsplit(v0, h0, l0); bfsplit(v1, h1, l1);
                sH[so + cp] = (uint32_t)h0 | ((uint32_t)h1 << 16);
                sL[so + cp] = (uint32_t)l0 | ((uint32_t)l1 << 16);
            }
        }
    }
    __syncthreads();

    float d[MT][NT][4];
#pragma unroll
    for (int i = 0; i < MT; i++)
#pragma unroll
        for (int j = 0; j < NT; j++)
#pragma unroll
            for (int q = 0; q < 4; q++) d[i][j][q] = 0.f;

    const uint32_t shu = smem_u32(smem);
    for (int t = 0; t < 9; t++) {
        uint4 bfr[KS][NT];
        {
            const uint4* wft = wf + (size_t)(t * KS * (NOC / 8)) * 32 + lane;
#pragma unroll
            for (int ks = 0; ks < KS; ks++)
#pragma unroll
                for (int j = 0; j < NT; j++)
                    bfr[ks][j] = wft[(size_t)(ks * (NOC / 8) + ng * NT + j) * 32];
        }
        const int tapbase = (t / 3) * 130 + (t % 3);
#pragma unroll
        for (int ks = 0; ks < KS; ks++) {
#pragma unroll
            for (int i = 0; i < MT; i++) {
                const int mm = m_base + i * 16;
                const int p0 = tapbase + mm + 2 * (mm >> 7);
                uint32_t aa = shu + (uint32_t)((p0 + (lane & 15)) * KPB
                                               + ks * 32 + (lane >> 4) * 16);
                uint32_t ah[4], al[4];
                ldsm4(ah, aa);
                ldsm4(al, aa + SLAB);
                // product-major: NT independent accumulators between reuses
#pragma unroll
                for (int j = 0; j < NT; j++) mma16816(d[i][j], ah, bfr[ks][j].x, bfr[ks][j].y);
#pragma unroll
                for (int j = 0; j < NT; j++) mma16816(d[i][j], al, bfr[ks][j].x, bfr[ks][j].y);
#pragma unroll
                for (int j = 0; j < NT; j++) mma16816(d[i][j], ah, bfr[ks][j].z, bfr[ks][j].w);
            }
        }
    }
    __syncthreads();   // slab reads done (smem reused for reductions)

    // epilogue (+ optional gn1/gn2 block partials)
    const int OV = 128 - (W_ - 128);   // 56
    float sacc[NT], s2acc[NT];         // GN1S: per-j (8-ch group aligned)
    float e2s[NT][2], e2q[NT][2];      // GN2S: per (j, oc parity)
#pragma unroll
    for (int j = 0; j < NT; j++) {
        sacc[j] = 0.f; s2acc[j] = 0.f;
        e2s[j][0] = e2s[j][1] = 0.f; e2q[j][0] = e2q[j][1] = 0.f;
    }
#pragma unroll
    for (int i = 0; i < MT; i++) {
        const int mr = m_base + i * 16 + (lane >> 2);
#pragma unroll
        for (int j = 0; j < NT; j++) {
            const int c0 = (ng * NT + j) * 8 + 2 * (lane & 3);
#pragma unroll
            for (int q = 0; q < 4; q++) {
                int m = mr + (q >> 1) * 8;
                int oc = c0 + (q & 1);
                int mx = m & 127;
                if (xt == 1 && mx < OV) continue;
                float v = d[i][j][q];
                if (RELU) v = fmaxf(v, 0.f);
                int y = y2 * 2 + (m >> 7);
                size_t off = ((size_t)b * NOC + oc) * HW_ + (size_t)y * W_ + x0 + mx;
                if (ADDRES) v += res[off];
                out[off] = v;
                if (GN1S) { sacc[j] += v; s2acc[j] += v * v; }
                if (GN2S) { e2s[j][q & 1] += v; e2q[j][q & 1] += v * v; }
            }
        }
    }
    if (GN1S) {
        float2* red = reinterpret_cast<float2*>(smem);   // [8 warps][NT]
#pragma unroll
        for (int j = 0; j < NT; j++) {
            float s = sacc[j], s2 = s2acc[j];
            for (int o = 16; o > 0; o >>= 1) {
                s += __shfl_down_sync(0xffffffffu, s, o);
                s2 += __shfl_down_sync(0xffffffffu, s2, o);
            }
            if (lane == 0) red[wrp * NT + j] = make_float2(s, s2);
        }
        __syncthreads();
        if (tid < 8) {
            int ng2 = tid >> 2, j = tid & 3;
            float s = 0.f, s2 = 0.f;
            for (int mg = 0; mg < 4; mg++) {
                float2 v = red[(mg * 2 + ng2) * NT + j];
                s += v.x; s2 += v.y;
            }
            int bid = b * 128 + xt * 64 + y2;
            g_p1[bid * 8 + tid] = make_float2(s, s2);
        }
    }
    if (GN2S) {
        // reduce over lanes with equal lane&3 (strides 16,8,4), lanes 0-3 hold per-oc sums
        float2* red = reinterpret_cast<float2*>(smem);   // [8][NT][2][4]
#pragma unroll
        for (int j = 0; j < NT; j++)
#pragma unroll
            for (int par = 0; par < 2; par++) {
                float s = e2s[j][par], s2 = e2q[j][par];
                for (int o = 16; o >= 4; o >>= 1) {
                    s += __shfl_down_sync(0xffffffffu, s, o);
                    s2 += __shfl_down_sync(0xffffffffu, s2, o);
                }
                if (lane < 4) red[((wrp * NT + j) * 2 + par) * 4 + lane] = make_float2(s, s2);
            }
        __syncthreads();
        if (tid < NOC) {   // NOC=48
            int oc = tid;
            int ngg = oc / (NT * 8);
            int j = (oc % (NT * 8)) / 8;
            int rem = oc & 7;
            int l4 = rem >> 1, par = rem & 1;
            float s = 0.f, s2 = 0.f;
            for (int mg = 0; mg < 4; mg++) {
                float2 v = red[(((mg * 2 + ngg) * NT + j) * 2 + par) * 4 + l4];
                s += v.x; s2 += v.y;
            }
            int bid = b * 128 + xt * 64 + y2;
            g_p2b[bid * 48 + oc] = make_float2(s, s2);
        }
    }
}

// ---------------- GN finalize kernels ----------------
__global__ void gn1fin_k(const float* __restrict__ gma, const float* __restrict__ bta) {
    int g = blockIdx.x, b = blockIdx.y;   // 128 threads
    float2 v = g_p1[(b * 128 + threadIdx.x) * 8 + g];
    float s = v.x, s2 = v.y;
    __shared__ float sa[4], sb[4];
    for (int o = 16; o > 0; o >>= 1) {
        s += __shfl_down_sync(0xffffffffu, s, o);
        s2 += __shfl_down_sync(0xffffffffu, s2, o);
    }
    int wrp = threadIdx.x >> 5, lane = threadIdx.x & 31;
    if (lane == 0) { sa[wrp] = s; sb[wrp] = s2; }
    __syncthreads();
    if (threadIdx.x == 0) {
        double S = 0, S2 = 0;
        for (int w = 0; w < 4; w++) { S += sa[w]; S2 += sb[w]; }
        const double Nel = 8.0 * HW_;
        double mu = S / Nel, var = S2 / Nel - mu * mu;
        float rs = rsqrtf((float)var + EPS_);
        for (int c = 0; c < 8; c++) {
            int ch = g * 8 + c;
            float scl = gma[ch] * rs;
            g_n1[(b * C2 + ch) * 2] = scl;
            g_n1[(b * C2 + ch) * 2 + 1] = bta[ch] - (float)mu * scl;
        }
    }
}
// gn2 finalize: sum 128 block-partials x 6 channels per group
__global__ void gn2fin_k(const float* __restrict__ gma, const float* __restrict__ bta) {
    int g = blockIdx.x, b = blockIdx.y;
    float s = 0.f, s2 = 0.f;
    for (int i = threadIdx.x; i < 128 * 6; i += 256) {
        int blk = i / 6, c = i % 6;
        float2 v = g_p2b[(b * 128 + blk) * 48 + g * 6 + c];
        s += v.x; s2 += v.y;
    }
    __shared__ float sa[8], sb[8];
    for (int o = 16; o > 0; o >>= 1) {
        s += __shfl_down_sync(0xffffffffu, s, o);
        s2 += __shfl_down_sync(0xffffffffu, s2, o);
    }
    int wrp = threadIdx.x >> 5, lane = threadIdx.x & 31;
    if (lane == 0) { sa[wrp] = s; sb[wrp] = s2; }
    __syncthreads();
    if (threadIdx.x == 0) {
        double S = 0, S2 = 0;
        for (int w = 0; w < 8; w++) { S += sa[w]; S2 += sb[w]; }
        const double Nel = 6.0 * HW_;
        double mu = S / Nel, var = S2 / Nel - mu * mu;
        float rs = rsqrtf((float)var + EPS_);
        for (int c = 0; c < 6; c++) {
            int ch = g * 6 + c;
            float scl = gma[ch] * rs;
            g_n2[(b * C1 + ch) * 2] = scl;
            g_n2[(b * C1 + ch) * 2 + 1] = bta[ch] - (float)mu * scl;
        }
    }
}
__global__ void gn3fin_k(const float* __restrict__ gma, const float* __restrict__ bta) {
    int g = blockIdx.x, b = blockIdx.y;
    float s = 0.f, s2 = 0.f;
    if (threadIdx.x < 150) {
        int c = threadIdx.x / 25, k = threadIdx.x % 25;
        float2 v = g_p3[(b * C1 + g * 6 + c) * 25 + k];
        s = v.x; s2 = v.y;
    }
    __shared__ float sa[5], sb[5];
    for (int o = 16; o > 0; o >>= 1) {
        s += __shfl_down_sync(0xffffffffu, s, o);
        s2 += __shfl_down_sync(0xffffffffu, s2, o);
    }
    int wrp = threadIdx.x >> 5, lane = threadIdx.x & 31;
    if (lane == 0) { sa[wrp] = s; sb[wrp] = s2; }
    __syncthreads();
    if (threadIdx.x == 0) {
        double S = 0, S2 = 0;
        for (int w = 0; w < 5; w++) { S += sa[w]; S2 += sb[w]; }
        const double Nel = 6.0 * HW_;
        double mu = S / Nel, var = S2 / Nel - mu * mu;
        float rs = rsqrtf((float)var + EPS_);
        for (int c = 0; c < 6; c++) {
            int ch = g * 6 + c;
            float scl = gma[ch] * rs;
            g_n3[(b * C1 + ch) * 2] = scl;
            g_n3[(b * C1 + ch) * 2 + 1] = bta[ch] - (float)mu * scl;
        }
    }
}

// ---------------- misc ----------------
__global__ void zero4_k(float4* p, int n4) {
    int i = blockIdx.x * blockDim.x + threadIdx.x;
    if (i < n4) p[i] = make_float4(0.f, 0.f, 0.f, 0.f);
}
__global__ void copy4_k(float4* dst, const float4* src, int n4) {
    int i = blockIdx.x * blockDim.x + threadIdx.x;
    if (i < n4) dst[i] = src[i];
}
__global__ void conv0_k(const float* __restrict__ x, const float* __restrict__ w,
                        const float* __restrict__ bias, float* __restrict__ out) {
    __shared__ float ws[48 * 9];
    __shared__ float bs[48];
    for (int i = threadIdx.x; i < 48 * 9; i += blockDim.x) ws[i] = w[i];
    for (int i = threadIdx.x; i < 48; i += blockDim.x) bs[i] = bias[i];
    __syncthreads();
    int t = blockIdx.x * blockDim.x + threadIdx.x;
    if (t >= B_ * HW_) return;
    int b = t / HW_;
    int pix = t % HW_;
    int y = pix / W_, xx = pix % W_;
    const float* xp = x + (size_t)b * HW_;
    float iv[9];
    int k = 0;
#pragma unroll
    for (int dy = 0; dy < 3; dy++)
#pragma unroll
        for (int dx = 0; dx < 3; dx++) {
            int gy = y + dy - 1, gx = xx + dx - 1;
            iv[k++] = (gy >= 0 && gy < H_ && gx >= 0 && gx < W_) ? xp[gy * W_ + gx] : 0.f;
        }
    for (int o = 0; o < 48; o++) {
        float a = bs[o];
#pragma unroll
        for (int kk = 0; kk < 9; kk++) a += ws[o * 9 + kk] * iv[kk];
        out[((size_t)b * 48 + o) * HW_ + pix] = a;
    }
}
__global__ void bn_reduce_k(const float* __restrict__ data, const float* __restrict__ gma,
                            const float* __restrict__ bta, float* __restrict__ bnP) {
    int c = blockIdx.x;
    double s = 0, s2 = 0;
    const int N4 = B_ * HWQ;
    const float4* d4 = reinterpret_cast<const float4*>(data);
    for (int t = threadIdx.x; t < N4; t += blockDim.x) {
        int b = t / HWQ, i = t % HWQ;
        float4 v = d4[(size_t)(b * C1 + c) * HWQ + i];
        s  += (double)(v.x + v.y + v.z + v.w);
        s2 += (double)(v.x * v.x + v.y * v.y + v.z * v.z + v.w * v.w);
    }
    __shared__ double sh1[512], sh2[512];
    sh1[threadIdx.x] = s; sh2[threadIdx.x] = s2;
    __syncthreads();
    for (int st = 256; st > 0; st >>= 1) {
        if (threadIdx.x < st) { sh1[threadIdx.x] += sh1[threadIdx.x + st]; sh2[threadIdx.x] += sh2[threadIdx.x + st]; }
        __syncthreads();
    }
    if (threadIdx.x == 0) {
        const int N = B_ * HW_;
        double mu = sh1[0] / N;
        double var = sh2[0] / N - mu * mu;
        float rs = rsqrtf((float)var + EPS_);
        float scl = gma[c] * rs;
        bnP[c * 2] = scl;
        bnP[c * 2 + 1] = bta[c] - (float)mu * scl;
    }
}
__global__ void bn_apply_k(const float* __restrict__ in, const float* __restrict__ bnP,
                           float* __restrict__ out) {
    int i = blockIdx.x * blockDim.x + threadIdx.x;
    if (i >= BD1Q) return;
    int c = (i / HWQ) % C1;
    float sc = bnP[c * 2], sh = bnP[c * 2 + 1];
    float4 v = reinterpret_cast<const float4*>(in)[i];
    v.x = v.x * sc + sh; v.y = v.y * sc + sh; v.z = v.z * sc + sh; v.w = v.w * sc + sh;
    reinterpret_cast<float4*>(out)[i] = v;
}

__global__ void k3_k(const float* __restrict__ z, const float* __restrict__ u,
                     const float* __restrict__ n2, float* __restrict__ w) {
    int i = blockIdx.x * blockDim.x + threadIdx.x;
    int b = i / D1Q;
    int c = (i / HWQ) % C1;
    float sc = n2[(b * C1 + c) * 2], sh = n2[(b * C1 + c) * 2 + 1];
    float4 uv = reinterpret_cast<const float4*>(u)[i];
    float4 zv = reinterpret_cast<const float4*>(z)[i];
    float4 o;
    o.x = fmaxf(zv.x + uv.x * sc + sh, 0.f);
    o.y = fmaxf(zv.y + uv.y * sc + sh, 0.f);
    o.z = fmaxf(zv.z + uv.z * sc + sh, 0.f);
    o.w = fmaxf(zv.w + uv.w * sc + sh, 0.f);
    reinterpret_cast<float4*>(w)[i] = o;
    float s = o.x + o.y + o.z + o.w;
    float s2 = o.x * o.x + o.y * o.y + o.z * o.z + o.w * o.w;
    __shared__ float sa[8], sb[8];
    for (int off = 16; off > 0; off >>= 1) {
        s += __shfl_down_sync(0xffffffffu, s, off);
        s2 += __shfl_down_sync(0xffffffffu, s2, off);
    }
    int wrp = threadIdx.x >> 5, lane = threadIdx.x & 31;
    if (lane == 0) { sa[wrp] = s; sb[wrp] = s2; }
    __syncthreads();
    if (threadIdx.x == 0) {
        float S = 0, S2 = 0;
        for (int ww = 0; ww < 8; ww++) { S += sa[ww]; S2 += sb[ww]; }
        g_p3[blockIdx.x] = make_float2(S, S2);
    }
}
template <bool GOUT>
__global__ void k4_k(const float* __restrict__ w, const float* __restrict__ n3,
                     const float* __restrict__ xslot, float* __restrict__ fout,
                     float* __restrict__ gout) {
    int i = blockIdx.x * blockDim.x + threadIdx.x;
    if (i >= BD1Q) return;
    int b = i / D1Q;
    int c = (i / HWQ) % C1;
    float sc = n3[(b * C1 + c) * 2], sh = n3[(b * C1 + c) * 2 + 1];
    float4 wv = reinterpret_cast<const float4*>(w)[i];
    float4 f;
    f.x = wv.x * sc + sh; f.y = wv.y * sc + sh;
    f.z = wv.z * sc + sh; f.w = wv.w * sc + sh;
    reinterpret_cast<float4*>(fout)[i] = f;
    if (GOUT) {
        float4 xv = reinterpret_cast<const float4*>(xslot)[i];
        reinterpret_cast<float4*>(gout)[i] =
            make_float4(f.x - xv.x, f.y - xv.y, f.z - xv.z, f.w - xv.w);
    }
}

template <int N>
__global__ void gram_k() {
    constexpr int NP = N * (N + 1) / 2;
    const int b = blockIdx.y;
    const int chunk = blockIdx.x;
    const size_t base = (size_t)b * D1Q + (size_t)chunk * PER4;
    const float4* G4 = reinterpret_cast<const float4*>(g_G);
    float acc[NP];
#pragma unroll
    for (int p = 0; p < NP; p++) acc[p] = 0.f;
    for (int it = 0; it < PER4 / 256; it++) {
        int i = threadIdx.x + it * 256;
        float4 gv[N];
#pragma unroll
        for (int s = 0; s < N; s++) gv[s] = G4[(size_t)s * BD1Q + base + i];
        int p = 0;
#pragma unroll
        for (int a2 = 0; a2 < N; a2++)
#pragma unroll
            for (int c2 = 0; c2 <= a2; c2++)
                acc[p++] += gv[a2].x * gv[c2].x + gv[a2].y * gv[c2].y
                          + gv[a2].z * gv[c2].z + gv[a2].w * gv[c2].w;
    }
    __shared__ float red[15][9];
    int wid = threadIdx.x >> 5, ln = threadIdx.x & 31;
#pragma unroll
    for (int p = 0; p < NP; p++) {
        float v = acc[p];
        for (int off = 16; off > 0; off >>= 1) v += __shfl_down_sync(0xffffffffu, v, off);
        if (ln == 0) red[p][wid] = v;
    }
    __syncthreads();
    if (threadIdx.x < NP) {
        float s = 0.f;
#pragma unroll
        for (int w = 0; w < 8; w++) s += red[threadIdx.x][w];
        g_Hpart[(b * NCHUNK + chunk) * 15 + threadIdx.x] = s;
    }
}
template <int N>
__global__ void hfin_k() {
    constexpr int NP = N * (N + 1) / 2;
    int b = blockIdx.x;
    int p = threadIdx.x;
    if (p >= NP) return;
    int i = 0, j = 0, q = p;
    for (int a2 = 0; a2 < N; a2++) {
        if (q <= a2) { i = a2; j = q; break; }
        q -= (a2 + 1);
    }
    float s = 0.f;
    for (int ch = 0; ch < NCHUNK; ch++) s += g_Hpart[(b * NCHUNK + ch) * 15 + p];
    g_Hm[(b * MH + i) * MH + j] = s;
    g_Hm[(b * MH + j) * MH + i] = s;
}
__global__ void solve_k(int n) {
    int b = threadIdx.x;
    if (b >= B_) return;
    const int m = n + 1;
    double A[6][7];
    for (int i = 0; i < m; i++)
        for (int j = 0; j < m; j++) A[i][j] = 0.0;
    for (int j = 1; j < m; j++) { A[0][j] = 1.0; A[j][0] = 1.0; }
    for (int i = 1; i < m; i++)
        for (int j = 1; j < m; j++)
            A[i][j] = (double)g_Hm[(b * MH + (i - 1)) * MH + (j - 1)] + (i == j ? 1e-4 : 0.0);
    for (int i = 0; i < m; i++) A[i][m] = (i == 0) ? 1.0 : 0.0;
    for (int col = 0; col < m; col++) {
        int piv = col;
        double best = fabs(A[col][col]);
        for (int r = col + 1; r < m; r++)
            if (fabs(A[r][col]) > best) { best = fabs(A[r][col]); piv = r; }
        if (piv != col)
            for (int j = col; j <= m; j++) { double t = A[col][j]; A[col][j] = A[piv][j]; A[piv][j] = t; }
        double dd = A[col][col];
        for (int r = col + 1; r < m; r++) {
            double f = A[r][col] / dd;
            for (int j = col; j <= m; j++) A[r][j] -= f * A[col][j];
        }
    }
    double xv[6];
    for (int r = m - 1; r >= 0; r--) {
        double s = A[r][m];
        for (int j = r + 1; j < m; j++) s -= A[r][j] * xv[j];
        xv[r] = s / A[r][r];
    }
    for (int i = 0; i < n; i++) g_alpha[b * MH + i] = (float)xv[i + 1];
}
template <int N>
__global__ void combine_k(int slot) {
    int i = blockIdx.x * blockDim.x + threadIdx.x;
    if (i >= BD1Q) return;
    int b = i / D1Q;
    const float4* F4 = reinterpret_cast<const float4*>(g_F);
    float4 v = make_float4(0.f, 0.f, 0.f, 0.f);
#pragma unroll
    for (int s = 0; s < N; s++) {
        float a = g_alpha[b * MH + s];
        float4 f = F4[(size_t)s * BD1Q + i];
        v.x += a * f.x; v.y += a * f.y; v.z += a * f.z; v.w += a * f.w;
    }
    reinterpret_cast<float4*>(g_X)[(size_t)slot * BD1Q + i] = v;
}
__global__ void fc_k(const float* __restrict__ z, const float* __restrict__ fw,
                     const float* __restrict__ fb, float* __restrict__ out) {
    __shared__ float ws[10 * 200];
    __shared__ float bb[10];
    for (int i = threadIdx.x; i < 2000; i += 256) ws[i] = fw[i];
    if (threadIdx.x < 10) bb[threadIdx.x] = fb[threadIdx.x];
    __syncthreads();
    int warp = threadIdx.x >> 5, lane = threadIdx.x & 31;
    int row = blockIdx.x * 8 + warp;
    if (row >= B_ * C1 * H_) return;
    const float* zr = z + (size_t)row * W_;
    float p[10];
#pragma unroll
    for (int o = 0; o < 10; o++) p[o] = 0.f;
    for (int col = lane; col < W_; col += 32) {
        float v = zr[col];
#pragma unroll
        for (int o = 0; o < 10; o++) p[o] += v * ws[o * 200 + col];
    }
#pragma unroll
    for (int o = 0; o < 10; o++) {
        float v = p[o];
        for (int off = 16; off > 0; off >>= 1) v += __shfl_down_sync(0xffffffffu, v, off);
        if (lane == 0) out[(size_t)row * 10 + o] = v + bb[o];
    }
}

// ---------------- host ----------------
static constexpr int SM1 = 2 * 520 * 112;   // 116480
static constexpr int SM2 = 2 * 520 * 144;   // 149760
using CVK = void(*)(const float*, const uint4*, const float*, const float*, float*);

struct FParams {
    const uint4 *wf1, *wf2;
    const float *gn1_g, *gn1_b, *gn2_g, *gn2_b, *gn3_g, *gn3_b;
    float *t64, *u48, *w48, *n1, *n2, *n3;
    const float* h;
};

static void run_f_c1(const float* zin, const FParams& P) {
    conv_mma_k<48, 3, 112, 64, 4, false, true, false, true, false><<<dim3(2, 64, 8), 256, SM1>>>(
        zin, P.wf1, nullptr, nullptr, P.t64);
}
static void run_f_rest(const float* zin, const float* xslot, float* fout, float* gout,
                       const FParams& P) {
    const int EQ = BD1Q / 256;
    gn1fin_k<<<dim3(8, 8), 128>>>(P.gn1_g, P.gn1_b);
    conv_mma_k<64, 4, 144, 48, 3, true, false, true, false, true><<<dim3(2, 64, 8), 256, SM2>>>(
        P.t64, P.wf2, P.n1, P.h, P.u48);
    gn2fin_k<<<dim3(8, 8), 256>>>(P.gn2_g, P.gn2_b);
    k3_k<<<EQ, 256>>>(zin, P.u48, P.n2, P.w48);
    gn3fin_k<<<dim3(8, 8), 160>>>(P.gn3_g, P.gn3_b);
    if (gout)
        k4_k<true><<<EQ, 256>>>(P.w48, P.n3, xslot, fout, gout);
    else
        k4_k<false><<<EQ, 256>>>(P.w48, P.n3, nullptr, fout, nullptr);
}
static void run_f(const float* zin, const float* xslot, float* fout, float* gout,
                  const FParams& P) {
    run_f_c1(zin, P);
    run_f_rest(zin, xslot, fout, gout, P);
}

extern "C" void kernel_launch(void* const* d_in, const int* in_sizes, int n_in,
                              void* d_out, int out_size) {
    const float* x       = (const float*)d_in[0];
    const float* conv0_w = (const float*)d_in[1];
    const float* conv0_b = (const float*)d_in[2];
    const float* bn_g    = (const float*)d_in[3];
    const float* bn_b    = (const float*)d_in[4];
    const float* conv1_w = (const float*)d_in[5];
    const float* conv2_w = (const float*)d_in[6];
    const float* gn1_g   = (const float*)d_in[7];
    const float* gn1_b   = (const float*)d_in[8];
    const float* gn2_g   = (const float*)d_in[9];
    const float* gn2_b   = (const float*)d_in[10];
    const float* gn3_g   = (const float*)d_in[11];
    const float* gn3_b   = (const float*)d_in[12];
    const float* fc_w    = (const float*)d_in[13];
    const float* fc_b    = (const float*)d_in[14];
    float* out = (float*)d_out;

    cudaFuncSetAttribute((CVK)conv_mma_k<48, 3, 112, 64, 4, false, true, false, true, false>,
                         cudaFuncAttributeMaxDynamicSharedMemorySize, SM1);
    cudaFuncSetAttribute((CVK)conv_mma_k<64, 4, 144, 48, 3, true, false, true, false, true>,
                         cudaFuncAttributeMaxDynamicSharedMemorySize, SM2);

    float *pX, *pF, *pG, *ph, *pt64, *pu48, *pw48, *pzfin, *pn1, *pn2, *pn3, *pbnP;
    uint4 *pwf1, *pwf2;
    cudaGetSymbolAddress((void**)&pX, g_X);
    cudaGetSymbolAddress((void**)&pF, g_F);
    cudaGetSymbolAddress((void**)&pG, g_G);
    cudaGetSymbolAddress((void**)&ph, g_h);
    cudaGetSymbolAddress((void**)&pt64, g_t64);
    cudaGetSymbolAddress((void**)&pu48, g_u48);
    cudaGetSymbolAddress((void**)&pw48, g_w48);
    cudaGetSymbolAddress((void**)&pzfin, g_zfin);
    cudaGetSymbolAddress((void**)&pn1, g_n1);
    cudaGetSymbolAddress((void**)&pn2, g_n2);
    cudaGetSymbolAddress((void**)&pn3, g_n3);
    cudaGetSymbolAddress((void**)&pbnP, g_bnP);
    cudaGetSymbolAddress((void**)&pwf1, g_wf1);
    cudaGetSymbolAddress((void**)&pwf2, g_wf2);

    FParams P;
    P.wf1 = pwf1; P.wf2 = pwf2;
    P.gn1_g = gn1_g; P.gn1_b = gn1_b;
    P.gn2_g = gn2_g; P.gn2_b = gn2_b;
    P.gn3_g = gn3_g; P.gn3_b = gn3_b;
    P.t64 = pt64; P.u48 = pu48; P.w48 = pw48;
    P.n1 = pn1; P.n2 = pn2; P.n3 = pn3;
    P.h = ph;

    const int EQ = BD1Q / 256;

    // ordered so launch #4 is conv_mma_k (ncu diagnostic)
    pack_frag_k<<<27, 256>>>(conv1_w, pwf1, C1, C2, 3);
    pack_frag_k<<<27, 256>>>(conv2_w, pwf2, C2, C1, 4);
    zero4_k<<<EQ, 256>>>((float4*)pX, BD1Q);
    run_f_c1(pX, P);                                   // launch #4: conv1 on z=0
    conv0_k<<<(B_ * HW_) / 256, 256>>>(x, conv0_w, conv0_b, pu48);
    bn_reduce_k<<<48, 512>>>(pu48, bn_g, bn_b, pbnP);
    bn_apply_k<<<EQ, 256>>>(pu48, pbnP, ph);
    run_f_rest(pX, pX, pF, pG, P);

    copy4_k<<<EQ, 256>>>((float4*)(pX + (size_t)BD1_), (const float4*)pF, BD1Q);
    run_f(pX + (size_t)BD1_, pX + (size_t)BD1_, pF + (size_t)BD1_, pG + (size_t)BD1_, P);

    for (int k = 2; k < MAXIT; k++) {
        int n = (k < MH) ? k : MH;
        int s = k % MH;
        switch (n) {
            case 2: gram_k<2><<<dim3(NCHUNK, 8), 256>>>(); hfin_k<2><<<8, 32>>>(); break;
            case 3: gram_k<3><<<dim3(NCHUNK, 8), 256>>>(); hfin_k<3><<<8, 32>>>(); break;
            case 4: gram_k<4><<<dim3(NCHUNK, 8), 256>>>(); hfin_k<4><<<8, 32>>>(); break;
            default: gram_k<5><<<dim3(NCHUNK, 8), 256>>>(); hfin_k<5><<<8, 32>>>(); break;
        }
        solve_k<<<1, 8>>>(n);
        switch (n) {
            case 2: combine_k<2><<<EQ, 256>>>(s); break;
            case 3: combine_k<3><<<EQ, 256>>>(s); break;
            case 4: combine_k<4><<<EQ, 256>>>(s); break;
            default: combine_k<5><<<EQ, 256>>>(s); break;
        }
        run_f(pX + (size_t)s * BD1_, pX + (size_t)s * BD1_,
              pF + (size_t)s * BD1_, pG + (size_t)s * BD1_, P);
    }

    run_f(pX + (size_t)4 * BD1_, nullptr, pzfin, nullptr, P);
    fc_k<<<(B_ * C1 * H_) / 8, 256>>>(pzfin, fc_w, fc_b, out);
    (void)in_sizes; (void)n_in; (void)out_size;
}

// round 14
// speedup vs baseline: 1.0252x; 1.0252x over previous
#include <cuda_runtime.h>
#include <cuda_bf16.h>
#include <math.h>
#include <stdint.h>

static constexpr int B_   = 8;
static constexpr int H_   = 128;
static constexpr int W_   = 200;
static constexpr int HW_  = H_ * W_;
static constexpr int C1   = 48;
static constexpr int C2   = 64;
static constexpr int D1_  = C1 * HW_;
static constexpr int BD1_ = B_ * D1_;
static constexpr int BD2_ = B_ * C2 * HW_;
static constexpr int MH   = 5;
static constexpr int MAXIT = 25;
static constexpr float EPS_ = 1e-5f;
static constexpr int D1Q  = D1_ / 4;
static constexpr int BD1Q = BD1_ / 4;
static constexpr int HWQ  = HW_ / 4;
static constexpr int NCHUNK = 100;
static constexpr int PER4   = D1Q / NCHUNK;

__device__ alignas(16) float g_X[(size_t)MH * BD1_];
__device__ alignas(16) float g_F[(size_t)MH * BD1_];
__device__ alignas(16) float g_G[(size_t)MH * BD1_];
__device__ alignas(16) float g_h[BD1_];
__device__ alignas(16) float g_t64[BD2_];
__device__ alignas(16) float g_u48[BD1_];
__device__ alignas(16) float g_w48[BD1_];
__device__ alignas(16) float g_zfin[BD1_];
__device__ float g_n1[B_ * C2 * 2];
__device__ float g_n2[B_ * C1 * 2];
__device__ float g_n3[B_ * C1 * 2];
__device__ float g_bnP[C1 * 2];
__device__ float g_Hm[B_ * MH * MH];
__device__ float g_alpha[B_ * MH];
__device__ float g_Hpart[B_ * NCHUNK * 15];
__device__ float2 g_p1[1024 * 8];
__device__ float2 g_p2[8 * 8 * 16];
__device__ float2 g_p3[9600];
// B-fragment tables: [tap][ks][oc8][lane] -> uint4(bh0,bh1,bl0,bl1)
__device__ alignas(16) uint4 g_wf1[9 * 3 * 8 * 32];
__device__ alignas(16) uint4 g_wf2[9 * 4 * 6 * 32];

__device__ __forceinline__ uint32_t smem_u32(const void* p) {
    uint32_t a;
    asm("{ .reg .u64 t; cvta.to.shared.u64 t, %1; cvt.u32.u64 %0, t; }" : "=r"(a) : "l"(p));
    return a;
}
__device__ __forceinline__ void ldsm4(uint32_t* r, uint32_t addr) {
    asm volatile("ldmatrix.sync.aligned.m8n8.x4.shared.b16 {%0,%1,%2,%3}, [%4];"
                 : "=r"(r[0]), "=r"(r[1]), "=r"(r[2]), "=r"(r[3]) : "r"(addr));
}
__device__ __forceinline__ void mma16816(float* d, const uint32_t* a, uint32_t b0, uint32_t b1) {
    asm volatile("mma.sync.aligned.m16n8k16.row.col.f32.bf16.bf16.f32 "
                 "{%0,%1,%2,%3}, {%4,%5,%6,%7}, {%8,%9}, {%0,%1,%2,%3};"
                 : "+f"(d[0]), "+f"(d[1]), "+f"(d[2]), "+f"(d[3])
                 : "r"(a[0]), "r"(a[1]), "r"(a[2]), "r"(a[3]), "r"(b0), "r"(b1));
}
__device__ __forceinline__ void bfsplit(float v, uint16_t& h, uint16_t& l) {
    __nv_bfloat16 hb = __float2bfloat16(v);
    __nv_bfloat16 lb = __float2bfloat16(v - __bfloat162float(hb));
    h = __bfloat16_as_ushort(hb); l = __bfloat16_as_ushort(lb);
}
__device__ __forceinline__ uint32_t packh(float a, float b) {
    __nv_bfloat16 ha = __float2bfloat16(a), hb = __float2bfloat16(b);
    return (uint32_t)__bfloat16_as_ushort(ha) | ((uint32_t)__bfloat16_as_ushort(hb) << 16);
}
__device__ __forceinline__ uint32_t packl(float a, float b) {
    __nv_bfloat16 ha = __float2bfloat16(a), hb = __float2bfloat16(b);
    float la = a - __bfloat162float(ha), lb = b - __bfloat162float(hb);
    return (uint32_t)__bfloat16_as_ushort(__float2bfloat16(la))
         | ((uint32_t)__bfloat16_as_ushort(__float2bfloat16(lb)) << 16);
}

__global__ void pack_frag_k(const float* __restrict__ w, uint4* __restrict__ wf,
                            int cin, int noc, int ksteps) {
    int i = blockIdx.x * blockDim.x + threadIdx.x;
    int total = 9 * ksteps * (noc / 8) * 32;
    if (i >= total) return;
    int l = i & 31;
    int rest = i >> 5;
    int j = rest % (noc / 8); rest /= (noc / 8);
    int ks = rest % ksteps;
    int t = rest / ksteps;
    int oc = j * 8 + (l >> 2);
    int cb = ks * 16 + (l & 3) * 2;
    float va = (cb     < cin) ? w[(oc * cin + cb) * 9 + t] : 0.f;
    float vb = (cb + 1 < cin) ? w[(oc * cin + cb + 1) * 9 + t] : 0.f;
    float vc = (cb + 8 < cin) ? w[(oc * cin + cb + 8) * 9 + t] : 0.f;
    float vd = (cb + 9 < cin) ? w[(oc * cin + cb + 9) * 9 + t] : 0.f;
    wf[i] = make_uint4(packh(va, vb), packh(vc, vd), packl(va, vb), packl(vc, vd));
}

// ============ mma.sync 3x3 conv: 2 rows/block, sync-free, A-fragment pipelined ============
// grid (2 xt, 64 y2, 8 b), 256 thr, 8 warps = 4 m-groups x 2 n-groups.
template <int CIN, int KS, int KPB, int NOC, int NT,
          bool NORMIN, bool RELU, bool ADDRES, bool GN1S>
__global__ __launch_bounds__(256, 1) void conv_mma_k(
    const float* __restrict__ in, const uint4* __restrict__ wf,
    const float* __restrict__ normP, const float* __restrict__ res,
    float* __restrict__ out) {
    extern __shared__ char smem[];
    constexpr int MT = 4;
    constexpr int NP   = 520;          // 4 slab rows x 130 px
    constexpr int KPW  = KPB / 4;
    constexpr int SLAB = NP * KPB;
    static_assert((KS * MT) % 2 == 0, "parity reset per tap");
    const int tid  = threadIdx.x;
    const int lane = tid & 31;
    const int wrp  = tid >> 5;
    const int xt = blockIdx.x;
    const int y2 = blockIdx.y;
    const int b  = blockIdx.z;
    const int x0 = xt ? (W_ - 128) : 0;
    const int m_base = (wrp >> 1) * (MT * 16);
    const int ng = wrp & 1;

    {
        uint4* z4 = reinterpret_cast<uint4*>(smem);
        for (int i = tid; i < 2 * SLAB / 16; i += 256) z4[i] = make_uint4(0, 0, 0, 0);
    }
    __syncthreads();

    {
        uint32_t* sH = reinterpret_cast<uint32_t*>(smem);
        uint32_t* sL = sH + SLAB / 4;
        const float* inB = in + (size_t)b * CIN * HW_;
        for (int pp = tid; pp < NP; pp += 256) {
            int r = pp / 130, col = pp - r * 130;
            int gy = y2 * 2 - 1 + r, gx = x0 - 1 + col;
            if (gy < 0 || gy >= H_ || gx < 0 || gx >= W_) continue;
            const float* p0 = inB + gy * W_ + gx;
            uint32_t so = pp * KPW;
#pragma unroll 4
            for (int cp = 0; cp < CIN / 2; cp++) {
                float v0 = __ldg(p0 + (size_t)(2 * cp) * HW_);
                float v1 = __ldg(p0 + (size_t)(2 * cp + 1) * HW_);
                if (NORMIN) {
                    const float* np0 = normP + (b * CIN + 2 * cp) * 2;
                    v0 = v0 * np0[0] + np0[1];
                    v1 = v1 * np0[2] + np0[3];
                }
                uint16_t h0, l0, h1, l1;
                bfsplit(v0, h0, l0); bfsplit(v1, h1, l1);
                sH[so + cp] = (uint32_t)h0 | ((uint32_t)h1 << 16);
                sL[so + cp] = (uint32_t)l0 | ((uint32_t)l1 << 16);
            }
        }
    }
    __syncthreads();

    float d[MT][NT][4];
#pragma unroll
    for (int i = 0; i < MT; i++)
#pragma unroll
        for (int j = 0; j < NT; j++)
#pragma unroll
            for (int q = 0; q < 4; q++) d[i][j][q] = 0.f;

    const uint32_t shu = smem_u32(smem);
    const int lm = (lane & 15);
    const int lhi = (lane >> 4) * 16;

    // A-fragment double buffer; parity resets each tap since KS*MT is even.
    uint32_t ahb[2][4], alb[2][4];
    {
        // prologue: (t=0, ks=0, i=0)
        const int mm = m_base;
        const int p0 = mm + 2 * (mm >> 7);
        uint32_t aa = shu + (uint32_t)((p0 + lm) * KPB + lhi);
        ldsm4(ahb[0], aa);
        ldsm4(alb[0], aa + SLAB);
    }

    for (int t = 0; t < 9; t++) {
        uint4 bfr[KS][NT];
        {
            const uint4* wft = wf + (size_t)(t * KS * (NOC / 8)) * 32 + lane;
#pragma unroll
            for (int ks = 0; ks < KS; ks++)
#pragma unroll
                for (int j = 0; j < NT; j++)
                    bfr[ks][j] = wft[(size_t)(ks * (NOC / 8) + ng * NT + j) * 32];
        }
#pragma unroll
        for (int ks = 0; ks < KS; ks++) {
#pragma unroll
            for (int i = 0; i < MT; i++) {
                const int pr = (ks * MT + i) & 1;   // compile-time in unrolled body
                // prefetch next step's fragments (possibly next tap)
                {
                    int ni = i + 1, nks = ks, nt2 = t;
                    if (ni == MT) { ni = 0; nks++; if (nks == KS) { nks = 0; nt2++; } }
                    if (nt2 < 9) {
                        const int mm2 = m_base + ni * 16;
                        const int p2 = (nt2 / 3) * 130 + (nt2 - (nt2 / 3) * 3)
                                       + mm2 + 2 * (mm2 >> 7);
                        uint32_t aa2 = shu + (uint32_t)((p2 + lm) * KPB + nks * 32 + lhi);
                        ldsm4(ahb[pr ^ 1], aa2);
                        ldsm4(alb[pr ^ 1], aa2 + SLAB);
                    }
                }
#pragma unroll
                for (int j = 0; j < NT; j++) {
                    mma16816(d[i][j], ahb[pr], bfr[ks][j].x, bfr[ks][j].y);
                    mma16816(d[i][j], alb[pr], bfr[ks][j].x, bfr[ks][j].y);
                    mma16816(d[i][j], ahb[pr], bfr[ks][j].z, bfr[ks][j].w);
                }
            }
        }
    }
    __syncthreads();   // slab reads done (smem reused for GN1S reduction)

    // epilogue (+ optional gn1 block partials)
    const int OV = 128 - (W_ - 128);   // 56
    float sacc[NT], s2acc[NT];
#pragma unroll
    for (int j = 0; j < NT; j++) { sacc[j] = 0.f; s2acc[j] = 0.f; }
#pragma unroll
    for (int i = 0; i < MT; i++) {
        const int mr = m_base + i * 16 + (lane >> 2);
#pragma unroll
        for (int j = 0; j < NT; j++) {
            const int c0 = (ng * NT + j) * 8 + 2 * (lane & 3);
#pragma unroll
            for (int q = 0; q < 4; q++) {
                int m = mr + (q >> 1) * 8;
                int oc = c0 + (q & 1);
                int mx = m & 127;
                if (xt == 1 && mx < OV) continue;
                float v = d[i][j][q];
                if (RELU) v = fmaxf(v, 0.f);
                int y = y2 * 2 + (m >> 7);
                size_t off = ((size_t)b * NOC + oc) * HW_ + (size_t)y * W_ + x0 + mx;
                if (ADDRES) v += res[off];
                out[off] = v;
                if (GN1S) { sacc[j] += v; s2acc[j] += v * v; }
            }
        }
    }
    if (GN1S) {
        float2* red = reinterpret_cast<float2*>(smem);   // [8 warps][NT]
#pragma unroll
        for (int j = 0; j < NT; j++) {
            float s = sacc[j], s2 = s2acc[j];
            for (int o = 16; o > 0; o >>= 1) {
                s += __shfl_down_sync(0xffffffffu, s, o);
                s2 += __shfl_down_sync(0xffffffffu, s2, o);
            }
            if (lane == 0) red[wrp * NT + j] = make_float2(s, s2);
        }
        __syncthreads();
        if (tid < 8) {
            int ng2 = tid >> 2, j = tid & 3;
            float s = 0.f, s2 = 0.f;
            for (int mg = 0; mg < 4; mg++) {
                float2 v = red[(mg * 2 + ng2) * NT + j];
                s += v.x; s2 += v.y;
            }
            int bid = b * 128 + xt * 64 + y2;
            g_p1[bid * 8 + tid] = make_float2(s, s2);
        }
    }
}

// ---------------- GN finalize kernels ----------------
__global__ void gn1fin_k(const float* __restrict__ gma, const float* __restrict__ bta) {
    int g = blockIdx.x, b = blockIdx.y;   // 128 threads
    float2 v = g_p1[(b * 128 + threadIdx.x) * 8 + g];
    float s = v.x, s2 = v.y;
    __shared__ float sa[4], sb[4];
    for (int o = 16; o > 0; o >>= 1) {
        s += __shfl_down_sync(0xffffffffu, s, o);
        s2 += __shfl_down_sync(0xffffffffu, s2, o);
    }
    int wrp = threadIdx.x >> 5, lane = threadIdx.x & 31;
    if (lane == 0) { sa[wrp] = s; sb[wrp] = s2; }
    __syncthreads();
    if (threadIdx.x == 0) {
        double S = 0, S2 = 0;
        for (int w = 0; w < 4; w++) { S += sa[w]; S2 += sb[w]; }
        const double Nel = 8.0 * HW_;
        double mu = S / Nel, var = S2 / Nel - mu * mu;
        float rs = rsqrtf((float)var + EPS_);
        for (int c = 0; c < 8; c++) {
            int ch = g * 8 + c;
            float scl = gma[ch] * rs;
            g_n1[(b * C2 + ch) * 2] = scl;
            g_n1[(b * C2 + ch) * 2 + 1] = bta[ch] - (float)mu * scl;
        }
    }
}
__global__ void gn3fin_k(const float* __restrict__ gma, const float* __restrict__ bta) {
    int g = blockIdx.x, b = blockIdx.y;
    float s = 0.f, s2 = 0.f;
    if (threadIdx.x < 150) {
        int c = threadIdx.x / 25, k = threadIdx.x % 25;
        float2 v = g_p3[(b * C1 + g * 6 + c) * 25 + k];
        s = v.x; s2 = v.y;
    }
    __shared__ float sa[5], sb[5];
    for (int o = 16; o > 0; o >>= 1) {
        s += __shfl_down_sync(0xffffffffu, s, o);
        s2 += __shfl_down_sync(0xffffffffu, s2, o);
    }
    int wrp = threadIdx.x >> 5, lane = threadIdx.x & 31;
    if (lane == 0) { sa[wrp] = s; sb[wrp] = s2; }
    __syncthreads();
    if (threadIdx.x == 0) {
        double S = 0, S2 = 0;
        for (int w = 0; w < 5; w++) { S += sa[w]; S2 += sb[w]; }
        const double Nel = 6.0 * HW_;
        double mu = S / Nel, var = S2 / Nel - mu * mu;
        float rs = rsqrtf((float)var + EPS_);
        for (int c = 0; c < 6; c++) {
            int ch = g * 6 + c;
            float scl = gma[ch] * rs;
            g_n3[(b * C1 + ch) * 2] = scl;
            g_n3[(b * C1 + ch) * 2 + 1] = bta[ch] - (float)mu * scl;
        }
    }
}
__global__ void gn2s1_k(const float* __restrict__ u) {
    int g = blockIdx.x, b = blockIdx.y, ch = blockIdx.z;
    const float4* base = reinterpret_cast<const float4*>(u) + (size_t)(b * C1 + g * 6) * HWQ + ch * 2400;
    float s = 0.f, s2 = 0.f;
    for (int i = threadIdx.x; i < 2400; i += 256) {
        float4 v = base[i];
        s += v.x + v.y + v.z + v.w;
        s2 += v.x * v.x + v.y * v.y + v.z * v.z + v.w * v.w;
    }
    __shared__ float sa[8], sb[8];
    for (int o = 16; o > 0; o >>= 1) {
        s += __shfl_down_sync(0xffffffffu, s, o);
        s2 += __shfl_down_sync(0xffffffffu, s2, o);
    }
    int wrp = threadIdx.x >> 5, lane = threadIdx.x & 31;
    if (lane == 0) { sa[wrp] = s; sb[wrp] = s2; }
    __syncthreads();
    if (threadIdx.x == 0) {
        float S = 0, S2 = 0;
        for (int w = 0; w < 8; w++) { S += sa[w]; S2 += sb[w]; }
        g_p2[(b * 8 + g) * 16 + ch] = make_float2(S, S2);
    }
}
__global__ void gn2s2_k(const float* __restrict__ gma, const float* __restrict__ bta) {
    int g = blockIdx.x, b = blockIdx.y;
    float s = 0.f, s2 = 0.f;
    if (threadIdx.x < 16) {
        float2 v = g_p2[(b * 8 + g) * 16 + threadIdx.x];
        s = v.x; s2 = v.y;
    }
    for (int o = 8; o > 0; o >>= 1) {
        s += __shfl_down_sync(0xffffffffu, s, o);
        s2 += __shfl_down_sync(0xffffffffu, s2, o);
    }
    if (threadIdx.x == 0) {
        const double Nel = 6.0 * HW_;
        double mu = (double)s / Nel, var = (double)s2 / Nel - mu * mu;
        float rs = rsqrtf((float)var + EPS_);
        for (int c = 0; c < 6; c++) {
            int ch = g * 6 + c;
            float scl = gma[ch] * rs;
            g_n2[(b * C1 + ch) * 2] = scl;
            g_n2[(b * C1 + ch) * 2 + 1] = bta[ch] - (float)mu * scl;
        }
    }
}

// ---------------- misc ----------------
__global__ void zero4_k(float4* p, int n4) {
    int i = blockIdx.x * blockDim.x + threadIdx.x;
    if (i < n4) p[i] = make_float4(0.f, 0.f, 0.f, 0.f);
}
__global__ void copy4_k(float4* dst, const float4* src, int n4) {
    int i = blockIdx.x * blockDim.x + threadIdx.x;
    if (i < n4) dst[i] = src[i];
}
__global__ void conv0_k(const float* __restrict__ x, const float* __restrict__ w,
                        const float* __restrict__ bias, float* __restrict__ out) {
    __shared__ float ws[48 * 9];
    __shared__ float bs[48];
    for (int i = threadIdx.x; i < 48 * 9; i += blockDim.x) ws[i] = w[i];
    for (int i = threadIdx.x; i < 48; i += blockDim.x) bs[i] = bias[i];
    __syncthreads();
    int t = blockIdx.x * blockDim.x + threadIdx.x;
    if (t >= B_ * HW_) return;
    int b = t / HW_;
    int pix = t % HW_;
    int y = pix / W_, xx = pix % W_;
    const float* xp = x + (size_t)b * HW_;
    float iv[9];
    int k = 0;
#pragma unroll
    for (int dy = 0; dy < 3; dy++)
#pragma unroll
        for (int dx = 0; dx < 3; dx++) {
            int gy = y + dy - 1, gx = xx + dx - 1;
            iv[k++] = (gy >= 0 && gy < H_ && gx >= 0 && gx < W_) ? xp[gy * W_ + gx] : 0.f;
        }
    for (int o = 0; o < 48; o++) {
        float a = bs[o];
#pragma unroll
        for (int kk = 0; kk < 9; kk++) a += ws[o * 9 + kk] * iv[kk];
        out[((size_t)b * 48 + o) * HW_ + pix] = a;
    }
}
__global__ void bn_reduce_k(const float* __restrict__ data, const float* __restrict__ gma,
                            const float* __restrict__ bta, float* __restrict__ bnP) {
    int c = blockIdx.x;
    double s = 0, s2 = 0;
    const int N4 = B_ * HWQ;
    const float4* d4 = reinterpret_cast<const float4*>(data);
    for (int t = threadIdx.x; t < N4; t += blockDim.x) {
        int b = t / HWQ, i = t % HWQ;
        float4 v = d4[(size_t)(b * C1 + c) * HWQ + i];
        s  += (double)(v.x + v.y + v.z + v.w);
        s2 += (double)(v.x * v.x + v.y * v.y + v.z * v.z + v.w * v.w);
    }
    __shared__ double sh1[512], sh2[512];
    sh1[threadIdx.x] = s; sh2[threadIdx.x] = s2;
    __syncthreads();
    for (int st = 256; st > 0; st >>= 1) {
        if (threadIdx.x < st) { sh1[threadIdx.x] += sh1[threadIdx.x + st]; sh2[threadIdx.x] += sh2[threadIdx.x + st]; }
        __syncthreads();
    }
    if (threadIdx.x == 0) {
        const int N = B_ * HW_;
        double mu = sh1[0] / N;
        double var = sh2[0] / N - mu * mu;
        float rs = rsqrtf((float)var + EPS_);
        float scl = gma[c] * rs;
        bnP[c * 2] = scl;
        bnP[c * 2 + 1] = bta[c] - (float)mu * scl;
    }
}
__global__ void bn_apply_k(const float* __restrict__ in, const float* __restrict__ bnP,
                           float* __restrict__ out) {
    int i = blockIdx.x * blockDim.x + threadIdx.x;
    if (i >= BD1Q) return;
    int c = (i / HWQ) % C1;
    float sc = bnP[c * 2], sh = bnP[c * 2 + 1];
    float4 v = reinterpret_cast<const float4*>(in)[i];
    v.x = v.x * sc + sh; v.y = v.y * sc + sh; v.z = v.z * sc + sh; v.w = v.w * sc + sh;
    reinterpret_cast<float4*>(out)[i] = v;
}

__global__ void k3_k(const float* __restrict__ z, const float* __restrict__ u,
                     const float* __restrict__ n2, float* __restrict__ w) {
    int i = blockIdx.x * blockDim.x + threadIdx.x;
    int b = i / D1Q;
    int c = (i / HWQ) % C1;
    float sc = n2[(b * C1 + c) * 2], sh = n2[(b * C1 + c) * 2 + 1];
    float4 uv = reinterpret_cast<const float4*>(u)[i];
    float4 zv = reinterpret_cast<const float4*>(z)[i];
    float4 o;
    o.x = fmaxf(zv.x + uv.x * sc + sh, 0.f);
    o.y = fmaxf(zv.y + uv.y * sc + sh, 0.f);
    o.z = fmaxf(zv.z + uv.z * sc + sh, 0.f);
    o.w = fmaxf(zv.w + uv.w * sc + sh, 0.f);
    reinterpret_cast<float4*>(w)[i] = o;
    float s = o.x + o.y + o.z + o.w;
    float s2 = o.x * o.x + o.y * o.y + o.z * o.z + o.w * o.w;
    __shared__ float sa[8], sb[8];
    for (int off = 16; off > 0; off >>= 1) {
        s += __shfl_down_sync(0xffffffffu, s, off);
        s2 += __shfl_down_sync(0xffffffffu, s2, off);
    }
    int wrp = threadIdx.x >> 5, lane = threadIdx.x & 31;
    if (lane == 0) { sa[wrp] = s; sb[wrp] = s2; }
    __syncthreads();
    if (threadIdx.x == 0) {
        float S = 0, S2 = 0;
        for (int ww = 0; ww < 8; ww++) { S += sa[ww]; S2 += sb[ww]; }
        g_p3[blockIdx.x] = make_float2(S, S2);
    }
}
template <bool GOUT>
__global__ void k4_k(const float* __restrict__ w, const float* __restrict__ n3,
                     const float* __restrict__ xslot, float* __restrict__ fout,
                     float* __restrict__ gout) {
    int i = blockIdx.x * blockDim.x + threadIdx.x;
    if (i >= BD1Q) return;
    int b = i / D1Q;
    int c = (i / HWQ) % C1;
    float sc = n3[(b * C1 + c) * 2], sh = n3[(b * C1 + c) * 2 + 1];
    float4 wv = reinterpret_cast<const float4*>(w)[i];
    float4 f;
    f.x = wv.x * sc + sh; f.y = wv.y * sc + sh;
    f.z = wv.z * sc + sh; f.w = wv.w * sc + sh;
    reinterpret_cast<float4*>(fout)[i] = f;
    if (GOUT) {
        float4 xv = reinterpret_cast<const float4*>(xslot)[i];
        reinterpret_cast<float4*>(gout)[i] =
            make_float4(f.x - xv.x, f.y - xv.y, f.z - xv.z, f.w - xv.w);
    }
}

template <int N>
__global__ void gram_k() {
    constexpr int NP = N * (N + 1) / 2;
    const int b = blockIdx.y;
    const int chunk = blockIdx.x;
    const size_t base = (size_t)b * D1Q + (size_t)chunk * PER4;
    const float4* G4 = reinterpret_cast<const float4*>(g_G);
    float acc[NP];
#pragma unroll
    for (int p = 0; p < NP; p++) acc[p] = 0.f;
    for (int it = 0; it < PER4 / 256; it++) {
        int i = threadIdx.x + it * 256;
        float4 gv[N];
#pragma unroll
        for (int s = 0; s < N; s++) gv[s] = G4[(size_t)s * BD1Q + base + i];
        int p = 0;
#pragma unroll
        for (int a2 = 0; a2 < N; a2++)
#pragma unroll
            for (int c2 = 0; c2 <= a2; c2++)
                acc[p++] += gv[a2].x * gv[c2].x + gv[a2].y * gv[c2].y
                          + gv[a2].z * gv[c2].z + gv[a2].w * gv[c2].w;
    }
    __shared__ float red[15][9];
    int wid = threadIdx.x >> 5, ln = threadIdx.x & 31;
#pragma unroll
    for (int p = 0; p < NP; p++) {
        float v = acc[p];
        for (int off = 16; off > 0; off >>= 1) v += __shfl_down_sync(0xffffffffu, v, off);
        if (ln == 0) red[p][wid] = v;
    }
    __syncthreads();
    if (threadIdx.x < NP) {
        float s = 0.f;
#pragma unroll
        for (int w = 0; w < 8; w++) s += red[threadIdx.x][w];
        g_Hpart[(b * NCHUNK + chunk) * 15 + threadIdx.x] = s;
    }
}
template <int N>
__global__ void hfin_k() {
    constexpr int NP = N * (N + 1) / 2;
    int b = blockIdx.x;
    int p = threadIdx.x;
    if (p >= NP) return;
    int i = 0, j = 0, q = p;
    for (int a2 = 0; a2 < N; a2++) {
        if (q <= a2) { i = a2; j = q; break; }
        q -= (a2 + 1);
    }
    float s = 0.f;
    for (int ch = 0; ch < NCHUNK; ch++) s += g_Hpart[(b * NCHUNK + ch) * 15 + p];
    g_Hm[(b * MH + i) * MH + j] = s;
    g_Hm[(b * MH + j) * MH + i] = s;
}
__global__ void solve_k(int n) {
    int b = threadIdx.x;
    if (b >= B_) return;
    const int m = n + 1;
    double A[6][7];
    for (int i = 0; i < m; i++)
        for (int j = 0; j < m; j++) A[i][j] = 0.0;
    for (int j = 1; j < m; j++) { A[0][j] = 1.0; A[j][0] = 1.0; }
    for (int i = 1; i < m; i++)
        for (int j = 1; j < m; j++)
            A[i][j] = (double)g_Hm[(b * MH + (i - 1)) * MH + (j - 1)] + (i == j ? 1e-4 : 0.0);
    for (int i = 0; i < m; i++) A[i][m] = (i == 0) ? 1.0 : 0.0;
    for (int col = 0; col < m; col++) {
        int piv = col;
        double best = fabs(A[col][col]);
        for (int r = col + 1; r < m; r++)
            if (fabs(A[r][col]) > best) { best = fabs(A[r][col]); piv = r; }
        if (piv != col)
            for (int j = col; j <= m; j++) { double t = A[col][j]; A[col][j] = A[piv][j]; A[piv][j] = t; }
        double dd = A[col][col];
        for (int r = col + 1; r < m; r++) {
            double f = A[r][col] / dd;
            for (int j = col; j <= m; j++) A[r][j] -= f * A[col][j];
        }
    }
    double xv[6];
    for (int r = m - 1; r >= 0; r--) {
        double s = A[r][m];
        for (int j = r + 1; j < m; j++) s -= A[r][j] * xv[j];
        xv[r] = s / A[r][r];
    }
    for (int i = 0; i < n; i++) g_alpha[b * MH + i] = (float)xv[i + 1];
}
template <int N>
__global__ void combine_k(int slot) {
    int i = blockIdx.x * blockDim.x + threadIdx.x;
    if (i >= BD1Q) return;
    int b = i / D1Q;
    const float4* F4 = reinterpret_cast<const float4*>(g_F);
    float4 v = make_float4(0.f, 0.f, 0.f, 0.f);
#pragma unroll
    for (int s = 0; s < N; s++) {
        float a = g_alpha[b * MH + s];
        float4 f = F4[(size_t)s * BD1Q + i];
        v.x += a * f.x; v.y += a * f.y; v.z += a * f.z; v.w += a * f.w;
    }
    reinterpret_cast<float4*>(g_X)[(size_t)slot * BD1Q + i] = v;
}
__global__ void fc_k(const float* __restrict__ z, const float* __restrict__ fw,
                     const float* __restrict__ fb, float* __restrict__ out) {
    __shared__ float ws[10 * 200];
    __shared__ float bb[10];
    for (int i = threadIdx.x; i < 2000; i += 256) ws[i] = fw[i];
    if (threadIdx.x < 10) bb[threadIdx.x] = fb[threadIdx.x];
    __syncthreads();
    int warp = threadIdx.x >> 5, lane = threadIdx.x & 31;
    int row = blockIdx.x * 8 + warp;
    if (row >= B_ * C1 * H_) return;
    const float* zr = z + (size_t)row * W_;
    float p[10];
#pragma unroll
    for (int o = 0; o < 10; o++) p[o] = 0.f;
    for (int col = lane; col < W_; col += 32) {
        float v = zr[col];
#pragma unroll
        for (int o = 0; o < 10; o++) p[o] += v * ws[o * 200 + col];
    }
#pragma unroll
    for (int o = 0; o < 10; o++) {
        float v = p[o];
        for (int off = 16; off > 0; off >>= 1) v += __shfl_down_sync(0xffffffffu, v, off);
        if (lane == 0) out[(size_t)row * 10 + o] = v + bb[o];
    }
}

// ---------------- host ----------------
static constexpr int SM1 = 2 * 520 * 112;   // 116480
static constexpr int SM2 = 2 * 520 * 144;   // 149760
using CVK = void(*)(const float*, const uint4*, const float*, const float*, float*);

struct FParams {
    const uint4 *wf1, *wf2;
    const float *gn1_g, *gn1_b, *gn2_g, *gn2_b, *gn3_g, *gn3_b;
    float *t64, *u48, *w48, *n1, *n2, *n3;
    const float* h;
};

static void run_f_c1(const float* zin, const FParams& P) {
    conv_mma_k<48, 3, 112, 64, 4, false, true, false, true><<<dim3(2, 64, 8), 256, SM1>>>(
        zin, P.wf1, nullptr, nullptr, P.t64);
}
static void run_f_rest(const float* zin, const float* xslot, float* fout, float* gout,
                       const FParams& P) {
    const int EQ = BD1Q / 256;
    gn1fin_k<<<dim3(8, 8), 128>>>(P.gn1_g, P.gn1_b);
    conv_mma_k<64, 4, 144, 48, 3, true, false, true, false><<<dim3(2, 64, 8), 256, SM2>>>(
        P.t64, P.wf2, P.n1, P.h, P.u48);
    gn2s1_k<<<dim3(8, 8, 16), 256>>>(P.u48);
    gn2s2_k<<<dim3(8, 8), 32>>>(P.gn2_g, P.gn2_b);
    k3_k<<<EQ, 256>>>(zin, P.u48, P.n2, P.w48);
    gn3fin_k<<<dim3(8, 8), 160>>>(P.gn3_g, P.gn3_b);
    if (gout)
        k4_k<true><<<EQ, 256>>>(P.w48, P.n3, xslot, fout, gout);
    else
        k4_k<false><<<EQ, 256>>>(P.w48, P.n3, nullptr, fout, nullptr);
}
static void run_f(const float* zin, const float* xslot, float* fout, float* gout,
                  const FParams& P) {
    run_f_c1(zin, P);
    run_f_rest(zin, xslot, fout, gout, P);
}

extern "C" void kernel_launch(void* const* d_in, const int* in_sizes, int n_in,
                              void* d_out, int out_size) {
    const float* x       = (const float*)d_in[0];
    const float* conv0_w = (const float*)d_in[1];
    const float* conv0_b = (const float*)d_in[2];
    const float* bn_g    = (const float*)d_in[3];
    const float* bn_b    = (const float*)d_in[4];
    const float* conv1_w = (const float*)d_in[5];
    const float* conv2_w = (const float*)d_in[6];
    const float* gn1_g   = (const float*)d_in[7];
    const float* gn1_b   = (const float*)d_in[8];
    const float* gn2_g   = (const float*)d_in[9];
    const float* gn2_b   = (const float*)d_in[10];
    const float* gn3_g   = (const float*)d_in[11];
    const float* gn3_b   = (const float*)d_in[12];
    const float* fc_w    = (const float*)d_in[13];
    const float* fc_b    = (const float*)d_in[14];
    float* out = (float*)d_out;

    cudaFuncSetAttribute((CVK)conv_mma_k<48, 3, 112, 64, 4, false, true, false, true>,
                         cudaFuncAttributeMaxDynamicSharedMemorySize, SM1);
    cudaFuncSetAttribute((CVK)conv_mma_k<64, 4, 144, 48, 3, true, false, true, false>,
                         cudaFuncAttributeMaxDynamicSharedMemorySize, SM2);

    float *pX, *pF, *pG, *ph, *pt64, *pu48, *pw48, *pzfin, *pn1, *pn2, *pn3, *pbnP;
    uint4 *pwf1, *pwf2;
    cudaGetSymbolAddress((void**)&pX, g_X);
    cudaGetSymbolAddress((void**)&pF, g_F);
    cudaGetSymbolAddress((void**)&pG, g_G);
    cudaGetSymbolAddress((void**)&ph, g_h);
    cudaGetSymbolAddress((void**)&pt64, g_t64);
    cudaGetSymbolAddress((void**)&pu48, g_u48);
    cudaGetSymbolAddress((void**)&pw48, g_w48);
    cudaGetSymbolAddress((void**)&pzfin, g_zfin);
    cudaGetSymbolAddress((void**)&pn1, g_n1);
    cudaGetSymbolAddress((void**)&pn2, g_n2);
    cudaGetSymbolAddress((void**)&pn3, g_n3);
    cudaGetSymbolAddress((void**)&pbnP, g_bnP);
    cudaGetSymbolAddress((void**)&pwf1, g_wf1);
    cudaGetSymbolAddress((void**)&pwf2, g_wf2);

    FParams P;
    P.wf1 = pwf1; P.wf2 = pwf2;
    P.gn1_g = gn1_g; P.gn1_b = gn1_b;
    P.gn2_g = gn2_g; P.gn2_b = gn2_b;
    P.gn3_g = gn3_g; P.gn3_b = gn3_b;
    P.t64 = pt64; P.u48 = pu48; P.w48 = pw48;
    P.n1 = pn1; P.n2 = pn2; P.n3 = pn3;
    P.h = ph;

    const int EQ = BD1Q / 256;

    // ordered so launch #4 is conv_mma_k (ncu diagnostic)
    pack_frag_k<<<27, 256>>>(conv1_w, pwf1, C1, C2, 3);
    pack_frag_k<<<27, 256>>>(conv2_w, pwf2, C2, C1, 4);
    zero4_k<<<EQ, 256>>>((float4*)pX, BD1Q);
    run_f_c1(pX, P);                                   // launch #4: conv1 on z=0
    conv0_k<<<(B_ * HW_) / 256, 256>>>(x, conv0_w, conv0_b, pu48);
    bn_reduce_k<<<48, 512>>>(pu48, bn_g, bn_b, pbnP);
    bn_apply_k<<<EQ, 256>>>(pu48, pbnP, ph);
    run_f_rest(pX, pX, pF, pG, P);

    copy4_k<<<EQ, 256>>>((float4*)(pX + (size_t)BD1_), (const float4*)pF, BD1Q);
    run_f(pX + (size_t)BD1_, pX + (size_t)BD1_, pF + (size_t)BD1_, pG + (size_t)BD1_, P);

    for (int k = 2; k < MAXIT; k++) {
        int n = (k < MH) ? k : MH;
        int s = k % MH;
        switch (n) {
            case 2: gram_k<2><<<dim3(NCHUNK, 8), 256>>>(); hfin_k<2><<<8, 32>>>(); break;
            case 3: gram_k<3><<<dim3(NCHUNK, 8), 256>>>(); hfin_k<3><<<8, 32>>>(); break;
            case 4: gram_k<4><<<dim3(NCHUNK, 8), 256>>>(); hfin_k<4><<<8, 32>>>(); break;
            default: gram_k<5><<<dim3(NCHUNK, 8), 256>>>(); hfin_k<5><<<8, 32>>>(); break;
        }
        solve_k<<<1, 8>>>(n);
        switch (n) {
            case 2: combine_k<2><<<EQ, 256>>>(s); break;
            case 3: combine_k<3><<<EQ, 256>>>(s); break;
            case 4: combine_k<4><<<EQ, 256>>>(s); break;
            default: combine_k<5><<<EQ, 256>>>(s); break;
        }
        run_f(pX + (size_t)s * BD1_, pX + (size_t)s * BD1_,
              pF + (size_t)s * BD1_, pG + (size_t)s * BD1_, P);
    }

    run_f(pX + (size_t)4 * BD1_, nullptr, pzfin, nullptr, P);
    fc_k<<<(B_ * C1 * H_) / 8, 256>>>(pzfin, fc_w, fc_b, out);
    (void)in_sizes; (void)n_in; (void)out_size;
}

// round 16
// speedup vs baseline: 1.1737x; 1.1449x over previous
#include <cuda_runtime.h>
#include <cuda_bf16.h>
#include <math.h>
#include <stdint.h>

static constexpr int B_   = 8;
static constexpr int H_   = 128;
static constexpr int W_   = 200;
static constexpr int HW_  = H_ * W_;
static constexpr int C1   = 48;
static constexpr int C2   = 64;
static constexpr int D1_  = C1 * HW_;
static constexpr int BD1_ = B_ * D1_;
static constexpr int BD2_ = B_ * C2 * HW_;
static constexpr int MH   = 5;
static constexpr int MAXIT = 25;
static constexpr float EPS_ = 1e-5f;
static constexpr int D1Q  = D1_ / 4;
static constexpr int BD1Q = BD1_ / 4;
static constexpr int HWQ  = HW_ / 4;
static constexpr int NCHUNK = 100;
static constexpr int PER4   = D1Q / NCHUNK;

__device__ alignas(16) float g_X[(size_t)MH * BD1_];
__device__ alignas(16) float g_F[(size_t)MH * BD1_];
__device__ alignas(16) float g_G[(size_t)MH * BD1_];
__device__ alignas(16) float g_h[BD1_];
__device__ alignas(16) float g_t64[BD2_];
__device__ alignas(16) float g_u48[BD1_];
__device__ alignas(16) float g_w48[BD1_];
__device__ alignas(16) float g_zfin[BD1_];
__device__ float g_n1[B_ * C2 * 2];
__device__ float g_n2[B_ * C1 * 2];
__device__ float g_n3[B_ * C1 * 2];
__device__ float g_bnP[C1 * 2];
__device__ float g_Hm[B_ * MH * MH];
__device__ float g_alpha[B_ * MH];
__device__ float g_Hpart[B_ * NCHUNK * 15];
__device__ float2 g_p1[1024 * 8];
__device__ float2 g_p2[8 * 8 * 16];
__device__ float2 g_p3[9600];
// B-fragment tables: [tap][ks][oc8][lane] -> uint4(bh0,bh1,bl0,bl1)
__device__ alignas(16) uint4 g_wf1[9 * 3 * 8 * 32];
__device__ alignas(16) uint4 g_wf2[9 * 4 * 6 * 32];

__device__ __forceinline__ uint32_t smem_u32(const void* p) {
    uint32_t a;
    asm("{ .reg .u64 t; cvta.to.shared.u64 t, %1; cvt.u32.u64 %0, t; }" : "=r"(a) : "l"(p));
    return a;
}
__device__ __forceinline__ void ldsm4(uint32_t* r, uint32_t addr) {
    asm volatile("ldmatrix.sync.aligned.m8n8.x4.shared.b16 {%0,%1,%2,%3}, [%4];"
                 : "=r"(r[0]), "=r"(r[1]), "=r"(r[2]), "=r"(r[3]) : "r"(addr));
}
__device__ __forceinline__ void mma16816(float* d, const uint32_t* a, uint32_t b0, uint32_t b1) {
    asm volatile("mma.sync.aligned.m16n8k16.row.col.f32.bf16.bf16.f32 "
                 "{%0,%1,%2,%3}, {%4,%5,%6,%7}, {%8,%9}, {%0,%1,%2,%3};"
                 : "+f"(d[0]), "+f"(d[1]), "+f"(d[2]), "+f"(d[3])
                 : "r"(a[0]), "r"(a[1]), "r"(a[2]), "r"(a[3]), "r"(b0), "r"(b1));
}
__device__ __forceinline__ void bfsplit(float v, uint16_t& h, uint16_t& l) {
    __nv_bfloat16 hb = __float2bfloat16(v);
    __nv_bfloat16 lb = __float2bfloat16(v - __bfloat162float(hb));
    h = __bfloat16_as_ushort(hb); l = __bfloat16_as_ushort(lb);
}
__device__ __forceinline__ uint32_t packh(float a, float b) {
    __nv_bfloat16 ha = __float2bfloat16(a), hb = __float2bfloat16(b);
    return (uint32_t)__bfloat16_as_ushort(ha) | ((uint32_t)__bfloat16_as_ushort(hb) << 16);
}
__device__ __forceinline__ uint32_t packl(float a, float b) {
    __nv_bfloat16 ha = __float2bfloat16(a), hb = __float2bfloat16(b);
    float la = a - __bfloat162float(ha), lb = b - __bfloat162float(hb);
    return (uint32_t)__bfloat16_as_ushort(__float2bfloat16(la))
         | ((uint32_t)__bfloat16_as_ushort(__float2bfloat16(lb)) << 16);
}

__global__ void pack_frag_k(const float* __restrict__ w, uint4* __restrict__ wf,
                            int cin, int noc, int ksteps) {
    int i = blockIdx.x * blockDim.x + threadIdx.x;
    int total = 9 * ksteps * (noc / 8) * 32;
    if (i >= total) return;
    int l = i & 31;
    int rest = i >> 5;
    int j = rest % (noc / 8); rest /= (noc / 8);
    int ks = rest % ksteps;
    int t = rest / ksteps;
    int oc = j * 8 + (l >> 2);
    int cb = ks * 16 + (l & 3) * 2;
    float va = (cb     < cin) ? w[(oc * cin + cb) * 9 + t] : 0.f;
    float vb = (cb + 1 < cin) ? w[(oc * cin + cb + 1) * 9 + t] : 0.f;
    float vc = (cb + 8 < cin) ? w[(oc * cin + cb + 8) * 9 + t] : 0.f;
    float vd = (cb + 9 < cin) ? w[(oc * cin + cb + 9) * 9 + t] : 0.f;
    wf[i] = make_uint4(packh(va, vb), packh(vc, vd), packl(va, vb), packl(vc, vd));
}

// ======== mma.sync 3x3 conv: 2 rows/block, 512 thr, 16 warps (8 mg x 2 ng), MT=2 ========
// Sync-free tap loop (R8 structure); 4 warps/SMSP for latency hiding.
template <int CIN, int KS, int KPB, int NOC, int NT,
          bool NORMIN, bool RELU, bool ADDRES, bool GN1S>
__global__ __launch_bounds__(512, 1) void conv_mma_k(
    const float* __restrict__ in, const uint4* __restrict__ wf,
    const float* __restrict__ normP, const float* __restrict__ res,
    float* __restrict__ out) {
    extern __shared__ char smem[];
    constexpr int MT = 2;
    constexpr int NP   = 520;          // 4 slab rows x 130 px
    constexpr int KPW  = KPB / 4;
    constexpr int SLAB = NP * KPB;
    const int tid  = threadIdx.x;
    const int lane = tid & 31;
    const int wrp  = tid >> 5;         // 0..15
    const int xt = blockIdx.x;
    const int y2 = blockIdx.y;
    const int b  = blockIdx.z;
    const int x0 = xt ? (W_ - 128) : 0;
    const int mg = wrp >> 1;           // 0..7
    const int ng = wrp & 1;
    const int m_base = mg * (MT * 16); // 32 rows per m-group

    {
        uint4* z4 = reinterpret_cast<uint4*>(smem);
        for (int i = tid; i < 2 * SLAB / 16; i += 512) z4[i] = make_uint4(0, 0, 0, 0);
    }
    __syncthreads();

    {
        uint32_t* sH = reinterpret_cast<uint32_t*>(smem);
        uint32_t* sL = sH + SLAB / 4;
        const float* inB = in + (size_t)b * CIN * HW_;
        for (int pp = tid; pp < NP; pp += 512) {
            int r = pp / 130, col = pp - r * 130;
            int gy = y2 * 2 - 1 + r, gx = x0 - 1 + col;
            if (gy < 0 || gy >= H_ || gx < 0 || gx >= W_) continue;
            const float* p0 = inB + gy * W_ + gx;
            uint32_t so = pp * KPW;
#pragma unroll 4
            for (int cp = 0; cp < CIN / 2; cp++) {
                float v0 = __ldg(p0 + (size_t)(2 * cp) * HW_);
                float v1 = __ldg(p0 + (size_t)(2 * cp + 1) * HW_);
                if (NORMIN) {
                    const float* np0 = normP + (b * CIN + 2 * cp) * 2;
                    v0 = v0 * np0[0] + np0[1];
                    v1 = v1 * np0[2] + np0[3];
                }
                uint16_t h0, l0, h1, l1;
                bfsplit(v0, h0, l0); bfsplit(v1, h1, l1);
                sH[so + cp] = (uint32_t)h0 | ((uint32_t)h1 << 16);
                sL[so + cp] = (uint32_t)l0 | ((uint32_t)l1 << 16);
            }
        }
    }
    __syncthreads();

    float d[MT][NT][4];
#pragma unroll
    for (int i = 0; i < MT; i++)
#pragma unroll
        for (int j = 0; j < NT; j++)
#pragma unroll
            for (int q = 0; q < 4; q++) d[i][j][q] = 0.f;

    const uint32_t shu = smem_u32(smem);
    for (int t = 0; t < 9; t++) {
        // B fragments for this tap: coalesced 16B/lane loads, L2-resident table
        uint4 bfr[KS][NT];
        {
            const uint4* wft = wf + (size_t)(t * KS * (NOC / 8)) * 32 + lane;
#pragma unroll
            for (int ks = 0; ks < KS; ks++)
#pragma unroll
                for (int j = 0; j < NT; j++)
                    bfr[ks][j] = wft[(size_t)(ks * (NOC / 8) + ng * NT + j) * 32];
        }
        const int tapbase = (t / 3) * 130 + (t % 3);
#pragma unroll
        for (int ks = 0; ks < KS; ks++) {
#pragma unroll
            for (int i = 0; i < MT; i++) {
                const int mm = m_base + i * 16;
                const int p0 = tapbase + mm + 2 * (mm >> 7);
                uint32_t aa = shu + (uint32_t)((p0 + (lane & 15)) * KPB
                                               + ks * 32 + (lane >> 4) * 16);
                uint32_t ah[4], al[4];
                ldsm4(ah, aa);
                ldsm4(al, aa + SLAB);
#pragma unroll
                for (int j = 0; j < NT; j++) {
                    mma16816(d[i][j], ah, bfr[ks][j].x, bfr[ks][j].y);
                    mma16816(d[i][j], al, bfr[ks][j].x, bfr[ks][j].y);
                    mma16816(d[i][j], ah, bfr[ks][j].z, bfr[ks][j].w);
                }
            }
        }
    }
    __syncthreads();   // slab reads done (smem reused for GN1S reduction)

    // epilogue (+ optional gn1 block partials)
    const int OV = 128 - (W_ - 128);   // 56
    float sacc[NT], s2acc[NT];
#pragma unroll
    for (int j = 0; j < NT; j++) { sacc[j] = 0.f; s2acc[j] = 0.f; }
#pragma unroll
    for (int i = 0; i < MT; i++) {
        const int mr = m_base + i * 16 + (lane >> 2);
#pragma unroll
        for (int j = 0; j < NT; j++) {
            const int c0 = (ng * NT + j) * 8 + 2 * (lane & 3);
#pragma unroll
            for (int q = 0; q < 4; q++) {
                int m = mr + (q >> 1) * 8;
                int oc = c0 + (q & 1);
                int mx = m & 127;
                if (xt == 1 && mx < OV) continue;
                float v = d[i][j][q];
                if (RELU) v = fmaxf(v, 0.f);
                int y = y2 * 2 + (m >> 7);
                size_t off = ((size_t)b * NOC + oc) * HW_ + (size_t)y * W_ + x0 + mx;
                if (ADDRES) v += res[off];
                out[off] = v;
                if (GN1S) { sacc[j] += v; s2acc[j] += v * v; }
            }
        }
    }
    if (GN1S) {
        float2* red = reinterpret_cast<float2*>(smem);   // [16 warps][NT]
#pragma unroll
        for (int j = 0; j < NT; j++) {
            float s = sacc[j], s2 = s2acc[j];
            for (int o = 16; o > 0; o >>= 1) {
                s += __shfl_down_sync(0xffffffffu, s, o);
                s2 += __shfl_down_sync(0xffffffffu, s2, o);
            }
            if (lane == 0) red[wrp * NT + j] = make_float2(s, s2);
        }
        __syncthreads();
        if (tid < 8) {   // 8 groups of 8 channels (NT=4, NG=2)
            int ng2 = tid >> 2, j = tid & 3;
            float s = 0.f, s2 = 0.f;
            for (int m2 = 0; m2 < 8; m2++) {
                float2 v = red[(m2 * 2 + ng2) * NT + j];
                s += v.x; s2 += v.y;
            }
            int bid = b * 128 + xt * 64 + y2;
            g_p1[bid * 8 + tid] = make_float2(s, s2);
        }
    }
}

// ---------------- GN finalize kernels ----------------
__global__ void gn1fin_k(const float* __restrict__ gma, const float* __restrict__ bta) {
    int g = blockIdx.x, b = blockIdx.y;   // 128 threads
    float2 v = g_p1[(b * 128 + threadIdx.x) * 8 + g];
    float s = v.x, s2 = v.y;
    __shared__ float sa[4], sb[4];
    for (int o = 16; o > 0; o >>= 1) {
        s += __shfl_down_sync(0xffffffffu, s, o);
        s2 += __shfl_down_sync(0xffffffffu, s2, o);
    }
    int wrp = threadIdx.x >> 5, lane = threadIdx.x & 31;
    if (lane == 0) { sa[wrp] = s; sb[wrp] = s2; }
    __syncthreads();
    if (threadIdx.x == 0) {
        double S = 0, S2 = 0;
        for (int w = 0; w < 4; w++) { S += sa[w]; S2 += sb[w]; }
        const double Nel = 8.0 * HW_;
        double mu = S / Nel, var = S2 / Nel - mu * mu;
        float rs = rsqrtf((float)var + EPS_);
        for (int c = 0; c < 8; c++) {
            int ch = g * 8 + c;
            float scl = gma[ch] * rs;
            g_n1[(b * C2 + ch) * 2] = scl;
            g_n1[(b * C2 + ch) * 2 + 1] = bta[ch] - (float)mu * scl;
        }
    }
}
__global__ void gn3fin_k(const float* __restrict__ gma, const float* __restrict__ bta) {
    int g = blockIdx.x, b = blockIdx.y;
    float s = 0.f, s2 = 0.f;
    if (threadIdx.x < 150) {
        int c = threadIdx.x / 25, k = threadIdx.x % 25;
        float2 v = g_p3[(b * C1 + g * 6 + c) * 25 + k];
        s = v.x; s2 = v.y;
    }
    __shared__ float sa[5], sb[5];
    for (int o = 16; o > 0; o >>= 1) {
        s += __shfl_down_sync(0xffffffffu, s, o);
        s2 += __shfl_down_sync(0xffffffffu, s2, o);
    }
    int wrp = threadIdx.x >> 5, lane = threadIdx.x & 31;
    if (lane == 0) { sa[wrp] = s; sb[wrp] = s2; }
    __syncthreads();
    if (threadIdx.x == 0) {
        double S = 0, S2 = 0;
        for (int w = 0; w < 5; w++) { S += sa[w]; S2 += sb[w]; }
        const double Nel = 6.0 * HW_;
        double mu = S / Nel, var = S2 / Nel - mu * mu;
        float rs = rsqrtf((float)var + EPS_);
        for (int c = 0; c < 6; c++) {
            int ch = g * 6 + c;
            float scl = gma[ch] * rs;
            g_n3[(b * C1 + ch) * 2] = scl;
            g_n3[(b * C1 + ch) * 2 + 1] = bta[ch] - (float)mu * scl;
        }
    }
}
__global__ void gn2s1_k(const float* __restrict__ u) {
    int g = blockIdx.x, b = blockIdx.y, ch = blockIdx.z;
    const float4* base = reinterpret_cast<const float4*>(u) + (size_t)(b * C1 + g * 6) * HWQ + ch * 2400;
    float s = 0.f, s2 = 0.f;
    for (int i = threadIdx.x; i < 2400; i += 256) {
        float4 v = base[i];
        s += v.x + v.y + v.z + v.w;
        s2 += v.x * v.x + v.y * v.y + v.z * v.z + v.w * v.w;
    }
    __shared__ float sa[8], sb[8];
    for (int o = 16; o > 0; o >>= 1) {
        s += __shfl_down_sync(0xffffffffu, s, o);
        s2 += __shfl_down_sync(0xffffffffu, s2, o);
    }
    int wrp = threadIdx.x >> 5, lane = threadIdx.x & 31;
    if (lane == 0) { sa[wrp] = s; sb[wrp] = s2; }
    __syncthreads();
    if (threadIdx.x == 0) {
        float S = 0, S2 = 0;
        for (int w = 0; w < 8; w++) { S += sa[w]; S2 += sb[w]; }
        g_p2[(b * 8 + g) * 16 + ch] = make_float2(S, S2);
    }
}
__global__ void gn2s2_k(const float* __restrict__ gma, const float* __restrict__ bta) {
    int g = blockIdx.x, b = blockIdx.y;
    float s = 0.f, s2 = 0.f;
    if (threadIdx.x < 16) {
        float2 v = g_p2[(b * 8 + g) * 16 + threadIdx.x];
        s = v.x; s2 = v.y;
    }
    for (int o = 8; o > 0; o >>= 1) {
        s += __shfl_down_sync(0xffffffffu, s, o);
        s2 += __shfl_down_sync(0xffffffffu, s2, o);
    }
    if (threadIdx.x == 0) {
        const double Nel = 6.0 * HW_;
        double mu = (double)s / Nel, var = (double)s2 / Nel - mu * mu;
        float rs = rsqrtf((float)var + EPS_);
        for (int c = 0; c < 6; c++) {
            int ch = g * 6 + c;
            float scl = gma[ch] * rs;
            g_n2[(b * C1 + ch) * 2] = scl;
            g_n2[(b * C1 + ch) * 2 + 1] = bta[ch] - (float)mu * scl;
        }
    }
}

// ---------------- misc ----------------
__global__ void zero4_k(float4* p, int n4) {
    int i = blockIdx.x * blockDim.x + threadIdx.x;
    if (i < n4) p[i] = make_float4(0.f, 0.f, 0.f, 0.f);
}
__global__ void copy4_k(float4* dst, const float4* src, int n4) {
    int i = blockIdx.x * blockDim.x + threadIdx.x;
    if (i < n4) dst[i] = src[i];
}
__global__ void conv0_k(const float* __restrict__ x, const float* __restrict__ w,
                        const float* __restrict__ bias, float* __restrict__ out) {
    __shared__ float ws[48 * 9];
    __shared__ float bs[48];
    for (int i = threadIdx.x; i < 48 * 9; i += blockDim.x) ws[i] = w[i];
    for (int i = threadIdx.x; i < 48; i += blockDim.x) bs[i] = bias[i];
    __syncthreads();
    int t = blockIdx.x * blockDim.x + threadIdx.x;
    if (t >= B_ * HW_) return;
    int b = t / HW_;
    int pix = t % HW_;
    int y = pix / W_, xx = pix % W_;
    const float* xp = x + (size_t)b * HW_;
    float iv[9];
    int k = 0;
#pragma unroll
    for (int dy = 0; dy < 3; dy++)
#pragma unroll
        for (int dx = 0; dx < 3; dx++) {
            int gy = y + dy - 1, gx = xx + dx - 1;
            iv[k++] = (gy >= 0 && gy < H_ && gx >= 0 && gx < W_) ? xp[gy * W_ + gx] : 0.f;
        }
    for (int o = 0; o < 48; o++) {
        float a = bs[o];
#pragma unroll
        for (int kk = 0; kk < 9; kk++) a += ws[o * 9 + kk] * iv[kk];
        out[((size_t)b * 48 + o) * HW_ + pix] = a;
    }
}
__global__ void bn_reduce_k(const float* __restrict__ data, const float* __restrict__ gma,
                            const float* __restrict__ bta, float* __restrict__ bnP) {
    int c = blockIdx.x;
    double s = 0, s2 = 0;
    const int N4 = B_ * HWQ;
    const float4* d4 = reinterpret_cast<const float4*>(data);
    for (int t = threadIdx.x; t < N4; t += blockDim.x) {
        int b = t / HWQ, i = t % HWQ;
        float4 v = d4[(size_t)(b * C1 + c) * HWQ + i];
        s  += (double)(v.x + v.y + v.z + v.w);
        s2 += (double)(v.x * v.x + v.y * v.y + v.z * v.z + v.w * v.w);
    }
    __shared__ double sh1[512], sh2[512];
    sh1[threadIdx.x] = s; sh2[threadIdx.x] = s2;
    __syncthreads();
    for (int st = 256; st > 0; st >>= 1) {
        if (threadIdx.x < st) { sh1[threadIdx.x] += sh1[threadIdx.x + st]; sh2[threadIdx.x] += sh2[threadIdx.x + st]; }
        __syncthreads();
    }
    if (threadIdx.x == 0) {
        const int N = B_ * HW_;
        double mu = sh1[0] / N;
        double var = sh2[0] / N - mu * mu;
        float rs = rsqrtf((float)var + EPS_);
        float scl = gma[c] * rs;
        bnP[c * 2] = scl;
        bnP[c * 2 + 1] = bta[c] - (float)mu * scl;
    }
}
__global__ void bn_apply_k(const float* __restrict__ in, const float* __restrict__ bnP,
                           float* __restrict__ out) {
    int i = blockIdx.x * blockDim.x + threadIdx.x;
    if (i >= BD1Q) return;
    int c = (i / HWQ) % C1;
    float sc = bnP[c * 2], sh = bnP[c * 2 + 1];
    float4 v = reinterpret_cast<const float4*>(in)[i];
    v.x = v.x * sc + sh; v.y = v.y * sc + sh; v.z = v.z * sc + sh; v.w = v.w * sc + sh;
    reinterpret_cast<float4*>(out)[i] = v;
}

__global__ void k3_k(const float* __restrict__ z, const float* __restrict__ u,
                     const float* __restrict__ n2, float* __restrict__ w) {
    int i = blockIdx.x * blockDim.x + threadIdx.x;
    int b = i / D1Q;
    int c = (i / HWQ) % C1;
    float sc = n2[(b * C1 + c) * 2], sh = n2[(b * C1 + c) * 2 + 1];
    float4 uv = reinterpret_cast<const float4*>(u)[i];
    float4 zv = reinterpret_cast<const float4*>(z)[i];
    float4 o;
    o.x = fmaxf(zv.x + uv.x * sc + sh, 0.f);
    o.y = fmaxf(zv.y + uv.y * sc + sh, 0.f);
    o.z = fmaxf(zv.z + uv.z * sc + sh, 0.f);
    o.w = fmaxf(zv.w + uv.w * sc + sh, 0.f);
    reinterpret_cast<float4*>(w)[i] = o;
    float s = o.x + o.y + o.z + o.w;
    float s2 = o.x * o.x + o.y * o.y + o.z * o.z + o.w * o.w;
    __shared__ float sa[8], sb[8];
    for (int off = 16; off > 0; off >>= 1) {
        s += __shfl_down_sync(0xffffffffu, s, off);
        s2 += __shfl_down_sync(0xffffffffu, s2, off);
    }
    int wrp = threadIdx.x >> 5, lane = threadIdx.x & 31;
    if (lane == 0) { sa[wrp] = s; sb[wrp] = s2; }
    __syncthreads();
    if (threadIdx.x == 0) {
        float S = 0, S2 = 0;
        for (int ww = 0; ww < 8; ww++) { S += sa[ww]; S2 += sb[ww]; }
        g_p3[blockIdx.x] = make_float2(S, S2);
    }
}
template <bool GOUT>
__global__ void k4_k(const float* __restrict__ w, const float* __restrict__ n3,
                     const float* __restrict__ xslot, float* __restrict__ fout,
                     float* __restrict__ gout) {
    int i = blockIdx.x * blockDim.x + threadIdx.x;
    if (i >= BD1Q) return;
    int b = i / D1Q;
    int c = (i / HWQ) % C1;
    float sc = n3[(b * C1 + c) * 2], sh = n3[(b * C1 + c) * 2 + 1];
    float4 wv = reinterpret_cast<const float4*>(w)[i];
    float4 f;
    f.x = wv.x * sc + sh; f.y = wv.y * sc + sh;
    f.z = wv.z * sc + sh; f.w = wv.w * sc + sh;
    reinterpret_cast<float4*>(fout)[i] = f;
    if (GOUT) {
        float4 xv = reinterpret_cast<const float4*>(xslot)[i];
        reinterpret_cast<float4*>(gout)[i] =
            make_float4(f.x - xv.x, f.y - xv.y, f.z - xv.z, f.w - xv.w);
    }
}

template <int N>
__global__ void gram_k() {
    constexpr int NP = N * (N + 1) / 2;
    const int b = blockIdx.y;
    const int chunk = blockIdx.x;
    const size_t base = (size_t)b * D1Q + (size_t)chunk * PER4;
    const float4* G4 = reinterpret_cast<const float4*>(g_G);
    float acc[NP];
#pragma unroll
    for (int p = 0; p < NP; p++) acc[p] = 0.f;
    for (int it = 0; it < PER4 / 256; it++) {
        int i = threadIdx.x + it * 256;
        float4 gv[N];
#pragma unroll
        for (int s = 0; s < N; s++) gv[s] = G4[(size_t)s * BD1Q + base + i];
        int p = 0;
#pragma unroll
        for (int a2 = 0; a2 < N; a2++)
#pragma unroll
            for (int c2 = 0; c2 <= a2; c2++)
                acc[p++] += gv[a2].x * gv[c2].x + gv[a2].y * gv[c2].y
                          + gv[a2].z * gv[c2].z + gv[a2].w * gv[c2].w;
    }
    __shared__ float red[15][9];
    int wid = threadIdx.x >> 5, ln = threadIdx.x & 31;
#pragma unroll
    for (int p = 0; p < NP; p++) {
        float v = acc[p];
        for (int off = 16; off > 0; off >>= 1) v += __shfl_down_sync(0xffffffffu, v, off);
        if (ln == 0) red[p][wid] = v;
    }
    __syncthreads();
    if (threadIdx.x < NP) {
        float s = 0.f;
#pragma unroll
        for (int w = 0; w < 8; w++) s += red[threadIdx.x][w];
        g_Hpart[(b * NCHUNK + chunk) * 15 + threadIdx.x] = s;
    }
}
template <int N>
__global__ void hfin_k() {
    constexpr int NP = N * (N + 1) / 2;
    int b = blockIdx.x;
    int p = threadIdx.x;
    if (p >= NP) return;
    int i = 0, j = 0, q = p;
    for (int a2 = 0; a2 < N; a2++) {
        if (q <= a2) { i = a2; j = q; break; }
        q -= (a2 + 1);
    }
    float s = 0.f;
    for (int ch = 0; ch < NCHUNK; ch++) s += g_Hpart[(b * NCHUNK + ch) * 15 + p];
    g_Hm[(b * MH + i) * MH + j] = s;
    g_Hm[(b * MH + j) * MH + i] = s;
}
__global__ void solve_k(int n) {
    int b = threadIdx.x;
    if (b >= B_) return;
    const int m = n + 1;
    double A[6][7];
    for (int i = 0; i < m; i++)
        for (int j = 0; j < m; j++) A[i][j] = 0.0;
    for (int j = 1; j < m; j++) { A[0][j] = 1.0; A[j][0] = 1.0; }
    for (int i = 1; i < m; i++)
        for (int j = 1; j < m; j++)
            A[i][j] = (double)g_Hm[(b * MH + (i - 1)) * MH + (j - 1)] + (i == j ? 1e-4 : 0.0);
    for (int i = 0; i < m; i++) A[i][m] = (i == 0) ? 1.0 : 0.0;
    for (int col = 0; col < m; col++) {
        int piv = col;
        double best = fabs(A[col][col]);
        for (int r = col + 1; r < m; r++)
            if (fabs(A[r][col]) > best) { best = fabs(A[r][col]); piv = r; }
        if (piv != col)
            for (int j = col; j <= m; j++) { double t = A[col][j]; A[col][j] = A[piv][j]; A[piv][j] = t; }
        double dd = A[col][col];
        for (int r = col + 1; r < m; r++) {
            double f = A[r][col] / dd;
            for (int j = col; j <= m; j++) A[r][j] -= f * A[col][j];
        }
    }
    double xv[6];
    for (int r = m - 1; r >= 0; r--) {
        double s = A[r][m];
        for (int j = r + 1; j < m; j++) s -= A[r][j] * xv[j];
        xv[r] = s / A[r][r];
    }
    for (int i = 0; i < n; i++) g_alpha[b * MH + i] = (float)xv[i + 1];
}
template <int N>
__global__ void combine_k(int slot) {
    int i = blockIdx.x * blockDim.x + threadIdx.x;
    if (i >= BD1Q) return;
    int b = i / D1Q;
    const float4* F4 = reinterpret_cast<const float4*>(g_F);
    float4 v = make_float4(0.f, 0.f, 0.f, 0.f);
#pragma unroll
    for (int s = 0; s < N; s++) {
        float a = g_alpha[b * MH + s];
        float4 f = F4[(size_t)s * BD1Q + i];
        v.x += a * f.x; v.y += a * f.y; v.z += a * f.z; v.w += a * f.w;
    }
    reinterpret_cast<float4*>(g_X)[(size_t)slot * BD1Q + i] = v;
}
__global__ void fc_k(const float* __restrict__ z, const float* __restrict__ fw,
                     const float* __restrict__ fb, float* __restrict__ out) {
    __shared__ float ws[10 * 200];
    __shared__ float bb[10];
    for (int i = threadIdx.x; i < 2000; i += 256) ws[i] = fw[i];
    if (threadIdx.x < 10) bb[threadIdx.x] = fb[threadIdx.x];
    __syncthreads();
    int warp = threadIdx.x >> 5, lane = threadIdx.x & 31;
    int row = blockIdx.x * 8 + warp;
    if (row >= B_ * C1 * H_) return;
    const float* zr = z + (size_t)row * W_;
    float p[10];
#pragma unroll
    for (int o = 0; o < 10; o++) p[o] = 0.f;
    for (int col = lane; col < W_; col += 32) {
        float v = zr[col];
#pragma unroll
        for (int o = 0; o < 10; o++) p[o] += v * ws[o * 200 + col];
    }
#pragma unroll
    for (int o = 0; o < 10; o++) {
        float v = p[o];
        for (int off = 16; off > 0; off >>= 1) v += __shfl_down_sync(0xffffffffu, v, off);
        if (lane == 0) out[(size_t)row * 10 + o] = v + bb[o];
    }
}

// ---------------- host ----------------
static constexpr int SM1 = 2 * 520 * 112;   // 116480
static constexpr int SM2 = 2 * 520 * 144;   // 149760
using CVK = void(*)(const float*, const uint4*, const float*, const float*, float*);

struct FParams {
    const uint4 *wf1, *wf2;
    const float *gn1_g, *gn1_b, *gn2_g, *gn2_b, *gn3_g, *gn3_b;
    float *t64, *u48, *w48, *n1, *n2, *n3;
    const float* h;
};

static void run_f_c1(const float* zin, const FParams& P) {
    conv_mma_k<48, 3, 112, 64, 4, false, true, false, true><<<dim3(2, 64, 8), 512, SM1>>>(
        zin, P.wf1, nullptr, nullptr, P.t64);
}
static void run_f_rest(const float* zin, const float* xslot, float* fout, float* gout,
                       const FParams& P) {
    const int EQ = BD1Q / 256;
    gn1fin_k<<<dim3(8, 8), 128>>>(P.gn1_g, P.gn1_b);
    conv_mma_k<64, 4, 144, 48, 3, true, false, true, false><<<dim3(2, 64, 8), 512, SM2>>>(
        P.t64, P.wf2, P.n1, P.h, P.u48);
    gn2s1_k<<<dim3(8, 8, 16), 256>>>(P.u48);
    gn2s2_k<<<dim3(8, 8), 32>>>(P.gn2_g, P.gn2_b);
    k3_k<<<EQ, 256>>>(zin, P.u48, P.n2, P.w48);
    gn3fin_k<<<dim3(8, 8), 160>>>(P.gn3_g, P.gn3_b);
    if (gout)
        k4_k<true><<<EQ, 256>>>(P.w48, P.n3, xslot, fout, gout);
    else
        k4_k<false><<<EQ, 256>>>(P.w48, P.n3, nullptr, fout, nullptr);
}
static void run_f(const float* zin, const float* xslot, float* fout, float* gout,
                  const FParams& P) {
    run_f_c1(zin, P);
    run_f_rest(zin, xslot, fout, gout, P);
}

extern "C" void kernel_launch(void* const* d_in, const int* in_sizes, int n_in,
                              void* d_out, int out_size) {
    const float* x       = (const float*)d_in[0];
    const float* conv0_w = (const float*)d_in[1];
    const float* conv0_b = (const float*)d_in[2];
    const float* bn_g    = (const float*)d_in[3];
    const float* bn_b    = (const float*)d_in[4];
    const float* conv1_w = (const float*)d_in[5];
    const float* conv2_w = (const float*)d_in[6];
    const float* gn1_g   = (const float*)d_in[7];
    const float* gn1_b   = (const float*)d_in[8];
    const float* gn2_g   = (const float*)d_in[9];
    const float* gn2_b   = (const float*)d_in[10];
    const float* gn3_g   = (const float*)d_in[11];
    const float* gn3_b   = (const float*)d_in[12];
    const float* fc_w    = (const float*)d_in[13];
    const float* fc_b    = (const float*)d_in[14];
    float* out = (float*)d_out;

    cudaFuncSetAttribute((CVK)conv_mma_k<48, 3, 112, 64, 4, false, true, false, true>,
                         cudaFuncAttributeMaxDynamicSharedMemorySize, SM1);
    cudaFuncSetAttribute((CVK)conv_mma_k<64, 4, 144, 48, 3, true, false, true, false>,
                         cudaFuncAttributeMaxDynamicSharedMemorySize, SM2);

    float *pX, *pF, *pG, *ph, *pt64, *pu48, *pw48, *pzfin, *pn1, *pn2, *pn3, *pbnP;
    uint4 *pwf1, *pwf2;
    cudaGetSymbolAddress((void**)&pX, g_X);
    cudaGetSymbolAddress((void**)&pF, g_F);
    cudaGetSymbolAddress((void**)&pG, g_G);
    cudaGetSymbolAddress((void**)&ph, g_h);
    cudaGetSymbolAddress((void**)&pt64, g_t64);
    cudaGetSymbolAddress((void**)&pu48, g_u48);
    cudaGetSymbolAddress((void**)&pw48, g_w48);
    cudaGetSymbolAddress((void**)&pzfin, g_zfin);
    cudaGetSymbolAddress((void**)&pn1, g_n1);
    cudaGetSymbolAddress((void**)&pn2, g_n2);
    cudaGetSymbolAddress((void**)&pn3, g_n3);
    cudaGetSymbolAddress((void**)&pbnP, g_bnP);
    cudaGetSymbolAddress((void**)&pwf1, g_wf1);
    cudaGetSymbolAddress((void**)&pwf2, g_wf2);

    FParams P;
    P.wf1 = pwf1; P.wf2 = pwf2;
    P.gn1_g = gn1_g; P.gn1_b = gn1_b;
    P.gn2_g = gn2_g; P.gn2_b = gn2_b;
    P.gn3_g = gn3_g; P.gn3_b = gn3_b;
    P.t64 = pt64; P.u48 = pu48; P.w48 = pw48;
    P.n1 = pn1; P.n2 = pn2; P.n3 = pn3;
    P.h = ph;

    const int EQ = BD1Q / 256;

    // ordered so launch #4 is conv_mma_k (ncu diagnostic)
    pack_frag_k<<<27, 256>>>(conv1_w, pwf1, C1, C2, 3);
    pack_frag_k<<<27, 256>>>(conv2_w, pwf2, C2, C1, 4);
    zero4_k<<<EQ, 256>>>((float4*)pX, BD1Q);
    run_f_c1(pX, P);                                   // launch #4: conv1 on z=0
    conv0_k<<<(B_ * HW_) / 256, 256>>>(x, conv0_w, conv0_b, pu48);
    bn_reduce_k<<<48, 512>>>(pu48, bn_g, bn_b, pbnP);
    bn_apply_k<<<EQ, 256>>>(pu48, pbnP, ph);
    run_f_rest(pX, pX, pF, pG, P);

    copy4_k<<<EQ, 256>>>((float4*)(pX + (size_t)BD1_), (const float4*)pF, BD1Q);
    run_f(pX + (size_t)BD1_, pX + (size_t)BD1_, pF + (size_t)BD1_, pG + (size_t)BD1_, P);

    for (int k = 2; k < MAXIT; k++) {
        int n = (k < MH) ? k : MH;
        int s = k % MH;
        switch (n) {
            case 2: gram_k<2><<<dim3(NCHUNK, 8), 256>>>(); hfin_k<2><<<8, 32>>>(); break;
            case 3: gram_k<3><<<dim3(NCHUNK, 8), 256>>>(); hfin_k<3><<<8, 32>>>(); break;
            case 4: gram_k<4><<<dim3(NCHUNK, 8), 256>>>(); hfin_k<4><<<8, 32>>>(); break;
            default: gram_k<5><<<dim3(NCHUNK, 8), 256>>>(); hfin_k<5><<<8, 32>>>(); break;
        }
        solve_k<<<1, 8>>>(n);
        switch (n) {
            case 2: combine_k<2><<<EQ, 256>>>(s); break;
            case 3: combine_k<3><<<EQ, 256>>>(s); break;
            case 4: combine_k<4><<<EQ, 256>>>(s); break;
            default: combine_k<5><<<EQ, 256>>>(s); break;
        }
        run_f(pX + (size_t)s * BD1_, pX + (size_t)s * BD1_,
              pF + (size_t)s * BD1_, pG + (size_t)s * BD1_, P);
    }

    run_f(pX + (size_t)4 * BD1_, nullptr, pzfin, nullptr, P);
    fc_k<<<(B_ * C1 * H_) / 8, 256>>>(pzfin, fc_w, fc_b, out);
    (void)in_sizes; (void)n_in; (void)out_size;
}